// round 13
// baseline (speedup 1.0000x reference)
#include <cuda_runtime.h>
#include <cuda_bf16.h>
#include <math.h>
#include <stdint.h>

// ---------------- problem constants ----------------
#define NPTS   74358      // 2 * 243 * 153
#define PK     153
#define PP     17
#define CC     128
#define MROWS  8262       // conv GEMM rows = 486*17

// feature levels: C_l = {48,96,192,384}, H = {96,48,24,12}, W = {72,36,18,9}
#define FT_OFF0 0
#define FT_OFF1 5971968
#define FT_OFF2 8957952
#define FT_OFF3 10450944
#define FT_TOTAL 11197440

// output regions (floats)
#define OUT_Q_OFF  0
#define OUT_V_OFF  9517824
#define OUT_SP_OFF 10575360

#define NCH     45          // K chunks of 16 channels; level edges at chunks 3/9/21
#define ASTRIDE 48          // bytes per point-row in A smem (24 bf16)
#define ONE_BF16X2 0x3F803F80u

// ---------------- device scratch ----------------
__device__ __nv_bfloat16 d_fTb[FT_TOTAL];                  // bf16 NHWC feature maps
__device__ __align__(16) uint32_t d_wBf[45 * 8 * 32 * 4];  // sampling B frags
__device__ float d_bsum[128];                              // 0.025 * sum(be_l)
__device__ __align__(16) uint32_t d_nqh[4758912];          // new_query hi bf16 pairs
__device__ __align__(16) uint32_t d_nql[4758912];          // new_query lo bf16 pairs
__device__ __align__(16) uint32_t d_cwh[72 * 8 * 32 * 4];  // conv W hi frags
__device__ __align__(16) uint32_t d_cwl[72 * 8 * 32 * 4];  // conv W lo frags

// ---------------- helpers ----------------
__device__ __forceinline__ uint32_t smem_to_u32(const void* p) {
    uint32_t a;
    asm("{ .reg .u64 t; cvta.to.shared.u64 t, %1; cvt.u32.u64 %0, t; }" : "=r"(a) : "l"(p));
    return a;
}
__device__ __forceinline__ void ldsm_x4(uint32_t* a, uint32_t saddr) {
    asm volatile("ldmatrix.sync.aligned.m8n8.x4.shared.b16 {%0,%1,%2,%3}, [%4];"
                 : "=r"(a[0]), "=r"(a[1]), "=r"(a[2]), "=r"(a[3]) : "r"(saddr));
}
__device__ __forceinline__ void mma16816(float* d, const uint32_t* a, uint32_t b0, uint32_t b1) {
    asm volatile(
        "mma.sync.aligned.m16n8k16.row.col.f32.bf16.bf16.f32 "
        "{%0,%1,%2,%3}, {%4,%5,%6,%7}, {%8,%9}, {%0,%1,%2,%3};"
        : "+f"(d[0]), "+f"(d[1]), "+f"(d[2]), "+f"(d[3])
        : "r"(a[0]), "r"(a[1]), "r"(a[2]), "r"(a[3]), "r"(b0), "r"(b1));
}
#define FMA_BF16X2(r, a, b, c) \
    asm("fma.rn.bf16x2 %0, %1, %2, %3;" : "=r"(r) : "r"(a), "r"(b), "r"(c))
#define CVT_BF16X2_BCAST(r, f) \
    asm("cvt.rn.bf16x2.f32 %0, %1, %2;" : "=r"(r) : "f"(f), "f"(f))

__device__ __forceinline__ uint32_t pack_hi(float x, float y) {
    __nv_bfloat16 hx = __float2bfloat16_rn(x);
    __nv_bfloat16 hy = __float2bfloat16_rn(y);
    return (uint32_t)__bfloat16_as_ushort(hx) | ((uint32_t)__bfloat16_as_ushort(hy) << 16);
}
__device__ __forceinline__ uint32_t pack_lo(float x, float y, uint32_t hi) {
    float hx = __bfloat162float(__ushort_as_bfloat16((unsigned short)(hi & 0xFFFF)));
    float hy = __bfloat162float(__ushort_as_bfloat16((unsigned short)(hi >> 16)));
    __nv_bfloat16 lx = __float2bfloat16_rn(x - hx);
    __nv_bfloat16 ly = __float2bfloat16_rn(y - hy);
    return (uint32_t)__bfloat16_as_ushort(lx) | ((uint32_t)__bfloat16_as_ushort(ly) << 16);
}

// ---------------- prep: feature transpose NCHW fp32 -> NHWC bf16 ----------------
__global__ void tposef_kernel(const float* __restrict__ in, int C, int H, int W, int outOff) {
    __shared__ float tile[32][33];
    int nz = blockIdx.z;
    int n = nz / H, y = nz % H;
    int x0 = blockIdx.x * 32, c0 = blockIdx.y * 32;
    int tx = threadIdx.x, ty = threadIdx.y;
#pragma unroll
    for (int k = 0; k < 4; k++) {
        int c = c0 + ty + 8 * k, x = x0 + tx;
        if (c < C && x < W)
            tile[ty + 8 * k][tx] = in[((size_t)(n * C + c) * H + y) * W + x];
    }
    __syncthreads();
#pragma unroll
    for (int k = 0; k < 4; k++) {
        int x = x0 + ty + 8 * k, c = c0 + tx;
        if (c < C && x < W)
            d_fTb[outOff + ((size_t)(n * H + y) * W + x) * C + c] =
                __float2bfloat16(tile[tx][ty + 8 * k]);
    }
}

// ---------------- prep: sampling B in mma fragment layout ----------------
__global__ void wbfprep_kernel(const float* __restrict__ we0, const float* __restrict__ we1,
                               const float* __restrict__ we2, const float* __restrict__ we3) {
    int e = blockIdx.x * 256 + threadIdx.x;
    if (e >= 45 * 8 * 32 * 4) return;
    int q = e & 3, lane = (e >> 2) & 31, np = (e >> 7) & 7, c = e >> 10;
    int t = q >> 1, reg = q & 1;
    int n = (np * 2 + t) * 8 + (lane >> 2);
    int k = c * 16 + reg * 8 + 2 * (lane & 3);
    uint32_t out = 0;
#pragma unroll
    for (int h = 0; h < 2; h++) {
        int ch = k + h;
        float v;
        if (ch < 48)       v = we0[n * 48 + ch];
        else if (ch < 144) v = we1[n * 96 + (ch - 48)];
        else if (ch < 336) v = we2[n * 192 + (ch - 144)];
        else               v = we3[n * 384 + (ch - 336)];
        __nv_bfloat16 b = __float2bfloat16(v);
        out |= (uint32_t)__bfloat16_as_ushort(b) << (16 * h);
    }
    d_wBf[e] = out;
}

// ---------------- prep: conv W hi/lo fragments ----------------
__global__ void wcfprep_kernel(const float* __restrict__ cw) {
    int e = blockIdx.x * 256 + threadIdx.x;
    if (e >= 72 * 8 * 32 * 4) return;
    int q = e & 3, lane = (e >> 2) & 31, np = (e >> 7) & 7, kc = e >> 10;
    int t = q >> 1, reg = q & 1;
    int n = (np * 2 + t) * 8 + (lane >> 2);
    int kf = kc * 16 + reg * 8 + 2 * (lane & 3);
    uint32_t oh = 0, ol = 0;
#pragma unroll
    for (int h = 0; h < 2; h++) {
        int kfe = kf + h;
        int k = kfe >> 7, c = kfe & 127;
        float v = cw[((size_t)n * 128 + c) * 9 + k];
        __nv_bfloat16 bh = __float2bfloat16_rn(v);
        float r = v - __bfloat162float(bh);
        __nv_bfloat16 bl = __float2bfloat16_rn(r);
        oh |= (uint32_t)__bfloat16_as_ushort(bh) << (16 * h);
        ol |= (uint32_t)__bfloat16_as_ushort(bl) << (16 * h);
    }
    d_cwh[e] = oh;
    d_cwl[e] = ol;
}

__global__ void bsum_kernel(const float* __restrict__ be0, const float* __restrict__ be1,
                            const float* __restrict__ be2, const float* __restrict__ be3) {
    int o = threadIdx.x;
    d_bsum[o] = 0.025f * (be0[o] + be1[o] + be2[o] + be3[o]);
}

// ---------------- sampling positions ----------------
__device__ __forceinline__ float dot4(float4 a, float4 b) {
    return a.x * b.x + a.y * b.y + a.z * b.z + a.w * b.w;
}

__global__ void pos_kernel(const float* __restrict__ query, const float* __restrict__ key,
                           const float* __restrict__ value,
                           const float* __restrict__ w_off, const float* __restrict__ b_off,
                           const float* __restrict__ w_attn, const float* __restrict__ b_attn,
                           float* __restrict__ spo) {
    int w = blockIdx.x * 8 + (threadIdx.x >> 5);
    if (w >= NPTS) return;
    int lane = threadIdx.x & 31;

    const float4* q4 = (const float4*)query;
    const float4* wo4 = (const float4*)w_off;
    float4 qv = q4[(size_t)w * 32 + lane];
    float d0 = dot4(qv, wo4[lane]);
    float d1 = dot4(qv, wo4[32 + lane]);

    int bt1 = w / PK;
    int p = (w % PK) % PP;
    const float4* v4 = (const float4*)value;
    const float4* wa4 = (const float4*)w_attn;
    float4 vv = v4[((size_t)bt1 * PP + p) * 32 + lane];
    float e0 = dot4(vv, wa4[lane]);
    float e1 = dot4(vv, wa4[32 + lane]);

#pragma unroll
    for (int s = 16; s; s >>= 1) {
        d0 += __shfl_xor_sync(0xFFFFFFFFu, d0, s);
        d1 += __shfl_xor_sync(0xFFFFFFFFu, d1, s);
        e0 += __shfl_xor_sync(0xFFFFFFFFu, e0, s);
        e1 += __shfl_xor_sync(0xFFFFFFFFu, e1, s);
    }
    if (lane == 0) {
        float o0 = tanhf(d0 + b_off[0]);
        float o1 = tanhf(d1 + b_off[1]);
        float l0 = e0 + b_attn[0], l1 = e1 + b_attn[1];
        float m = fmaxf(l0, l1);
        float x0 = expf(l0 - m), x1 = expf(l1 - m);
        float inv = 1.0f / (x0 + x1);
        spo[2 * w]     = key[2 * w]     + o0 * (x0 * inv);
        spo[2 * w + 1] = key[2 * w + 1] + o1 * (x1 * inv);
    }
}

// ---------------- bilinear geometry ----------------
__device__ __forceinline__ void geomcalc(bool valid, float gx, float gy, int n, int lvl,
                                         int4& o, float4& wv) {
    const int Hs[4] = {96, 48, 24, 12};
    const int Ws[4] = {72, 36, 18, 9};
    const int Cs[4] = {48, 96, 192, 384};
    const int FO[4] = {FT_OFF0, FT_OFF1, FT_OFF2, FT_OFF3};
    o = make_int4(0, 0, 0, 0);
    wv = make_float4(0.f, 0.f, 0.f, 0.f);
    if (!valid) return;
    int H = Hs[lvl], W = Ws[lvl], C = Cs[lvl];
    float ix = ((gx + 1.f) * (float)W - 1.f) * 0.5f;
    float iy = ((gy + 1.f) * (float)H - 1.f) * 0.5f;
    float fx = floorf(ix), fy = floorf(iy);
    int x0 = (int)fx, y0 = (int)fy;
    float wx1 = ix - fx, wy1 = iy - fy;
    float wx0 = 1.f - wx1, wy0 = 1.f - wy1;
    int base = FO[lvl] + n * (H * W * C);
    bool vx0 = (unsigned)x0 < (unsigned)W;
    bool vx1 = (unsigned)(x0 + 1) < (unsigned)W;
    bool vy0 = (unsigned)y0 < (unsigned)H;
    bool vy1 = (unsigned)(y0 + 1) < (unsigned)H;
    int r0 = y0 * W, r1 = r0 + W;
    if (vy0 && vx0) { o.x = base + (r0 + x0) * C;     wv.x = wy0 * wx0; }
    if (vy0 && vx1) { o.y = base + (r0 + x0 + 1) * C; wv.y = wy0 * wx1; }
    if (vy1 && vx0) { o.z = base + (r1 + x0) * C;     wv.z = wy1 * wx0; }
    if (vy1 && vx1) { o.w = base + (r1 + x0 + 1) * C; wv.w = wy1 * wx1; }
}

// ---------------- gather: thread pair per point; thread h owns y-row h corners ----------------
// Each thread loads 2 corners x 32B (16 channels, 32B-aligned: level C and chunk
// offsets are multiples of 16 elements). Partial bilinear sums merged via shfl_xor(1).
__device__ __forceinline__ void gather_load2(int cn, int tid, const int4* goff,
                                             const uint4* fp4, uint4 ca[4], int& cidx) {
    int h = tid & 1, pt = tid >> 1;
    int ch0 = cn * 16;
    int lvl = (ch0 < 48) ? 0 : (ch0 < 144) ? 1 : (ch0 < 336) ? 2 : 3;
    int gb  = (lvl == 0) ? 0 : (lvl == 1) ? 48 : (lvl == 2) ? 144 : 336;
    int chl = ch0 - gb;
    cidx = lvl * 128 + pt;
    int4 o = goff[cidx];
    int oa = (h ? o.z : o.x) + chl;   // corner (y-row h, x0)
    int ob = (h ? o.w : o.y) + chl;   // corner (y-row h, x0+1)
    ca[0] = fp4[(oa >> 3)];
    ca[1] = fp4[(oa >> 3) + 1];
    ca[2] = fp4[(ob >> 3)];
    ca[3] = fp4[(ob >> 3) + 1];
}

__device__ __forceinline__ void gather_store2(int tid, const float4* gwv,
                                              uint4 ca[4], int cidx,
                                              unsigned char* abuf) {
    int h = tid & 1, pt = tid >> 1;
    float4 wv = gwv[cidx];
    float wa = h ? wv.z : wv.x;
    float wb = h ? wv.w : wv.y;
    uint32_t wav, wbv;
    CVT_BF16X2_BCAST(wav, wa);
    CVT_BF16X2_BCAST(wbv, wb);
    const uint32_t* cw = (const uint32_t*)ca;  // [0..7]=corner a, [8..15]=corner b
    uint32_t s[8];
#pragma unroll
    for (int j = 0; j < 8; j++) {
        uint32_t t = 0;
        FMA_BF16X2(t, cw[j], wav, t);
        FMA_BF16X2(t, cw[8 + j], wbv, t);
        s[j] = t;
    }
    uint32_t one = ONE_BF16X2;
    uint32_t out[4];
#pragma unroll
    for (int i = 0; i < 4; i++) {
        uint32_t mine = h ? s[4 + i] : s[i];   // word I store
        uint32_t send = h ? s[i] : s[4 + i];   // word partner stores
        uint32_t p = __shfl_xor_sync(0xFFFFFFFFu, send, 1);
        FMA_BF16X2(mine, p, one, mine);
        out[i] = mine;
    }
    *(uint4*)(abuf + pt * ASTRIDE + h * 16) =
        make_uint4(out[0], out[1], out[2], out[3]);
}

// ---------------- main: mma.sync bf16 GEMM with sector-efficient gather ----------------
__global__ void __launch_bounds__(256, 2) main3_kernel(
    const float* __restrict__ sp, const float* __restrict__ query,
    float* __restrict__ outq) {
    __shared__ __align__(16) unsigned char abuf[2][128 * ASTRIDE];
    __shared__ int4 goff[512];
    __shared__ float4 gwv[512];

    int tid = threadIdx.x;
    int lane = tid & 31, wid = tid >> 5;
    int warp_m = wid & 3, warp_n = wid >> 2;
    int qb = blockIdx.x * 128;

#pragma unroll
    for (int s = 0; s < 2; s++) {
        int task = s * 256 + tid;
        int lvl = task >> 7, pt = task & 127;
        int q = qb + pt;
        bool valid = q < NPTS;
        float gx = 0.f, gy = 0.f;
        int n = 0;
        if (valid) {
            gx = sp[2 * q];
            gy = sp[2 * q + 1];
            n = q / 4131;
        }
        int4 o; float4 wv;
        geomcalc(valid, gx, gy, n, lvl, o, wv);
        goff[task] = o;
        gwv[task] = wv;
    }
    __syncthreads();

    float d[2][8][4];
#pragma unroll
    for (int i = 0; i < 2; i++)
#pragma unroll
        for (int j = 0; j < 8; j++)
#pragma unroll
            for (int k = 0; k < 4; k++) d[i][j][k] = 0.f;

    const uint4* fp4 = (const uint4*)d_fTb;
    const uint4* wB4 = (const uint4*)d_wBf;
    uint32_t abase = smem_to_u32(abuf);

    uint4 ca[4];
    int cidx;
    uint4 bcur[4], bnext[4];

    gather_load2(0, tid, goff, fp4, ca, cidx);
#pragma unroll
    for (int i = 0; i < 4; i++)
        bcur[i] = wB4[(warp_n * 4 + i) * 32 + lane];
    gather_store2(tid, gwv, ca, cidx, abuf[0]);
    __syncthreads();

#pragma unroll 1
    for (int c = 0; c < NCH; c++) {
        bool more = (c + 1) < NCH;
        if (more) {
            gather_load2(c + 1, tid, goff, fp4, ca, cidx);
#pragma unroll
            for (int i = 0; i < 4; i++)
                bnext[i] = wB4[((c + 1) * 8 + warp_n * 4 + i) * 32 + lane];
        }

        uint32_t a[2][4];
        uint32_t ab = abase + (c & 1) * (128 * ASTRIDE) +
                      (warp_m * 32 + (lane & 15)) * ASTRIDE + (lane >> 4) * 16;
        ldsm_x4(a[0], ab);
        ldsm_x4(a[1], ab + 16 * ASTRIDE);
#pragma unroll
        for (int nt = 0; nt < 8; nt++) {
            uint32_t b0 = (nt & 1) ? bcur[nt >> 1].z : bcur[nt >> 1].x;
            uint32_t b1 = (nt & 1) ? bcur[nt >> 1].w : bcur[nt >> 1].y;
            mma16816(d[0][nt], a[0], b0, b1);
            mma16816(d[1][nt], a[1], b0, b1);
        }

        if (more) {
            gather_store2(tid, gwv, ca, cidx, abuf[(c + 1) & 1]);
#pragma unroll
            for (int i = 0; i < 4; i++) bcur[i] = bnext[i];
        }
        __syncthreads();
    }

    // ---- epilogue: blend + store fp32 + hi/lo bf16 for the conv GEMM ----
#pragma unroll
    for (int mt = 0; mt < 2; mt++) {
#pragma unroll
        for (int rr = 0; rr < 2; rr++) {
            int q = qb + warp_m * 32 + mt * 16 + rr * 8 + (lane >> 2);
            if (q < NPTS) {
#pragma unroll
                for (int nt = 0; nt < 8; nt++) {
                    int o = warp_n * 64 + nt * 8 + 2 * (lane & 3);
                    float2 qv = *(const float2*)&query[(size_t)q * 128 + o];
                    float2 bsv = *(const float2*)&d_bsum[o];
                    float2 r;
                    r.x = 0.025f * d[mt][nt][rr * 2 + 0] + bsv.x + 0.9f * qv.x;
                    r.y = 0.025f * d[mt][nt][rr * 2 + 1] + bsv.y + 0.9f * qv.y;
                    *(float2*)&outq[(size_t)q * 128 + o] = r;
                    uint32_t hi = pack_hi(r.x, r.y);
                    uint32_t lo = pack_lo(r.x, r.y, hi);
                    int ui = q * 64 + (o >> 1);
                    d_nqh[ui] = hi;
                    d_nql[ui] = lo;
                }
            }
        }
    }
}

// ---------------- conv as split-precision bf16 GEMM ----------------
__global__ void __launch_bounds__(256) conv2_kernel(const float* __restrict__ conv_b,
                                                    float* __restrict__ nv) {
    __shared__ __align__(16) unsigned char ah[64 * 128];
    __shared__ __align__(16) unsigned char al[64 * 128];

    int tid = threadIdx.x;
    int lane = tid & 31, wid = tid >> 5;
    int warp_m = wid & 1, warp_n = wid >> 1;
    int m0 = blockIdx.x * 64;

    float d[2][4][4];
#pragma unroll
    for (int i = 0; i < 2; i++)
#pragma unroll
        for (int j = 0; j < 4; j++)
#pragma unroll
            for (int k = 0; k < 4; k++) d[i][j][k] = 0.f;

    const uint4* nqh4 = (const uint4*)d_nqh;
    const uint4* nql4 = (const uint4*)d_nql;
    const uint4* cwh4 = (const uint4*)d_cwh;
    const uint4* cwl4 = (const uint4*)d_cwl;
    uint32_t ahb = smem_to_u32(ah);
    uint32_t alb = smem_to_u32(al);

#pragma unroll 1
    for (int it = 0; it < 18; it++) {
        __syncthreads();
#pragma unroll
        for (int j = 0; j < 2; j++) {
            int idx = tid * 2 + j;
            int row = idx >> 3, cu = idx & 7;
            int m = m0 + row;
            int mc = (m < MROWS) ? m : MROWS - 1;
            int g = mc * 144 + it * 8 + cu;
            int soff = row * 128 + ((cu ^ (row & 7)) * 16);
            *(uint4*)(ah + soff) = nqh4[g];
            *(uint4*)(al + soff) = nql4[g];
        }
        __syncthreads();

#pragma unroll
        for (int kt = 0; kt < 4; kt++) {
            int kc = it * 4 + kt;
            uint4 bh0 = cwh4[((kc * 8) + 2 * warp_n + 0) * 32 + lane];
            uint4 bh1 = cwh4[((kc * 8) + 2 * warp_n + 1) * 32 + lane];
            uint4 bl0 = cwl4[((kc * 8) + 2 * warp_n + 0) * 32 + lane];
            uint4 bl1 = cwl4[((kc * 8) + 2 * warp_n + 1) * 32 + lane];
            uint32_t a_h[2][4], a_l[2][4];
#pragma unroll
            for (int mt = 0; mt < 2; mt++) {
                int row = warp_m * 32 + mt * 16 + (lane & 15);
                int cu = kt * 2 + (lane >> 4);
                uint32_t addr = row * 128 + ((cu ^ (row & 7)) * 16);
                ldsm_x4(a_h[mt], ahb + addr);
                ldsm_x4(a_l[mt], alb + addr);
            }
#pragma unroll
            for (int mt = 0; mt < 2; mt++) {
#pragma unroll
                for (int nt = 0; nt < 4; nt++) {
                    uint4 bh = (nt >> 1) ? bh1 : bh0;
                    uint4 bl = (nt >> 1) ? bl1 : bl0;
                    uint32_t bh_0 = (nt & 1) ? bh.z : bh.x;
                    uint32_t bh_1 = (nt & 1) ? bh.w : bh.y;
                    uint32_t bl_0 = (nt & 1) ? bl.z : bl.x;
                    uint32_t bl_1 = (nt & 1) ? bl.w : bl.y;
                    mma16816(d[mt][nt], a_h[mt], bh_0, bh_1);
                    mma16816(d[mt][nt], a_h[mt], bl_0, bl_1);
                    mma16816(d[mt][nt], a_l[mt], bh_0, bh_1);
                }
            }
        }
    }

#pragma unroll
    for (int mt = 0; mt < 2; mt++) {
#pragma unroll
        for (int rr = 0; rr < 2; rr++) {
            int m = m0 + warp_m * 32 + mt * 16 + rr * 8 + (lane >> 2);
            if (m < MROWS) {
#pragma unroll
                for (int nt = 0; nt < 4; nt++) {
                    int o = warp_n * 32 + nt * 8 + 2 * (lane & 3);
                    float2 cb = *(const float2*)&conv_b[o];
                    float2 r;
                    r.x = d[mt][nt][rr * 2 + 0] + cb.x;
                    r.y = d[mt][nt][rr * 2 + 1] + cb.y;
                    *(float2*)&nv[(size_t)m * 128 + o] = r;
                }
            }
        }
    }
}

// ---------------- launch ----------------
extern "C" void kernel_launch(void* const* d_in, const int* in_sizes, int n_in,
                              void* d_out, int out_size) {
    const float* f0     = (const float*)d_in[0];
    const float* f1     = (const float*)d_in[1];
    const float* f2     = (const float*)d_in[2];
    const float* f3     = (const float*)d_in[3];
    const float* query  = (const float*)d_in[4];
    const float* key    = (const float*)d_in[5];
    const float* value  = (const float*)d_in[6];
    const float* w_off  = (const float*)d_in[7];
    const float* b_off  = (const float*)d_in[8];
    const float* w_attn = (const float*)d_in[9];
    const float* b_attn = (const float*)d_in[10];
    const float* we0    = (const float*)d_in[11];
    const float* be0    = (const float*)d_in[12];
    const float* we1    = (const float*)d_in[13];
    const float* be1    = (const float*)d_in[14];
    const float* we2    = (const float*)d_in[15];
    const float* be2    = (const float*)d_in[16];
    const float* we3    = (const float*)d_in[17];
    const float* be3    = (const float*)d_in[18];
    const float* conv_w = (const float*)d_in[19];
    const float* conv_b = (const float*)d_in[20];

    float* out   = (float*)d_out;
    float* outQ  = out + OUT_Q_OFF;
    float* outV  = out + OUT_V_OFF;
    float* outSP = out + OUT_SP_OFF;

    dim3 tb(32, 8);
    tposef_kernel<<<dim3(3, 2, 18 * 96), tb>>>(f0, 48, 96, 72, FT_OFF0);
    tposef_kernel<<<dim3(2, 3, 18 * 48), tb>>>(f1, 96, 48, 36, FT_OFF1);
    tposef_kernel<<<dim3(1, 6, 18 * 24), tb>>>(f2, 192, 24, 18, FT_OFF2);
    tposef_kernel<<<dim3(1, 12, 18 * 12), tb>>>(f3, 384, 12, 9, FT_OFF3);

    wbfprep_kernel<<<180, 256>>>(we0, we1, we2, we3);
    wcfprep_kernel<<<288, 256>>>(conv_w);
    bsum_kernel<<<1, 128>>>(be0, be1, be2, be3);

    pos_kernel<<<9295, 256>>>(query, key, value, w_off, b_off, w_attn, b_attn, outSP);

    main3_kernel<<<(NPTS + 127) / 128, 256>>>(outSP, query, outQ);

    conv2_kernel<<<(MROWS + 63) / 64, 256>>>(conv_b, outV);
}

// round 14
// speedup vs baseline: 1.1537x; 1.1537x over previous
#include <cuda_runtime.h>
#include <cuda_bf16.h>
#include <math.h>
#include <stdint.h>

// ---------------- problem constants ----------------
#define NPTS   74358      // 2 * 243 * 153
#define PK     153
#define PP     17
#define CC     128
#define MROWS  8262       // conv GEMM rows = 486*17

// feature levels: C_l = {48,96,192,384}, H = {96,48,24,12}, W = {72,36,18,9}
#define FT_OFF0 0
#define FT_OFF1 5971968
#define FT_OFF2 8957952
#define FT_OFF3 10450944
#define FT_TOTAL 11197440

// output regions (floats)
#define OUT_Q_OFF  0
#define OUT_V_OFF  9517824
#define OUT_SP_OFF 10575360

#define NCH     45          // K chunks of 16 channels; level edges at chunks 3/9/21
#define ASTRIDE 48          // bytes per point-row in A smem (24 bf16)

// ---------------- device scratch ----------------
__device__ __nv_bfloat16 d_fTb[FT_TOTAL];                  // bf16 NHWC feature maps
__device__ __align__(16) uint32_t d_wBf[45 * 8 * 32 * 4];  // sampling B frags
__device__ float d_bsum[128];                              // 0.025 * sum(be_l)
__device__ __align__(16) uint32_t d_nqh[4758912];          // new_query hi bf16 pairs
__device__ __align__(16) uint32_t d_nql[4758912];          // new_query lo bf16 pairs
__device__ __align__(16) uint32_t d_cwh[72 * 8 * 32 * 4];  // conv W hi frags
__device__ __align__(16) uint32_t d_cwl[72 * 8 * 32 * 4];  // conv W lo frags

// ---------------- helpers ----------------
__device__ __forceinline__ uint32_t smem_to_u32(const void* p) {
    uint32_t a;
    asm("{ .reg .u64 t; cvta.to.shared.u64 t, %1; cvt.u32.u64 %0, t; }" : "=r"(a) : "l"(p));
    return a;
}
__device__ __forceinline__ void ldsm_x4(uint32_t* a, uint32_t saddr) {
    asm volatile("ldmatrix.sync.aligned.m8n8.x4.shared.b16 {%0,%1,%2,%3}, [%4];"
                 : "=r"(a[0]), "=r"(a[1]), "=r"(a[2]), "=r"(a[3]) : "r"(saddr));
}
__device__ __forceinline__ void mma16816(float* d, const uint32_t* a, uint32_t b0, uint32_t b1) {
    asm volatile(
        "mma.sync.aligned.m16n8k16.row.col.f32.bf16.bf16.f32 "
        "{%0,%1,%2,%3}, {%4,%5,%6,%7}, {%8,%9}, {%0,%1,%2,%3};"
        : "+f"(d[0]), "+f"(d[1]), "+f"(d[2]), "+f"(d[3])
        : "r"(a[0]), "r"(a[1]), "r"(a[2]), "r"(a[3]), "r"(b0), "r"(b1));
}
#define FMA_BF16X2(r, a, b, c) \
    asm("fma.rn.bf16x2 %0, %1, %2, %3;" : "=r"(r) : "r"(a), "r"(b), "r"(c))
#define CVT_BF16X2_BCAST(r, f) \
    asm("cvt.rn.bf16x2.f32 %0, %1, %2;" : "=r"(r) : "f"(f), "f"(f))

__device__ __forceinline__ uint32_t pack_hi(float x, float y) {
    __nv_bfloat16 hx = __float2bfloat16_rn(x);
    __nv_bfloat16 hy = __float2bfloat16_rn(y);
    return (uint32_t)__bfloat16_as_ushort(hx) | ((uint32_t)__bfloat16_as_ushort(hy) << 16);
}
__device__ __forceinline__ uint32_t pack_lo(float x, float y, uint32_t hi) {
    float hx = __bfloat162float(__ushort_as_bfloat16((unsigned short)(hi & 0xFFFF)));
    float hy = __bfloat162float(__ushort_as_bfloat16((unsigned short)(hi >> 16)));
    __nv_bfloat16 lx = __float2bfloat16_rn(x - hx);
    __nv_bfloat16 ly = __float2bfloat16_rn(y - hy);
    return (uint32_t)__bfloat16_as_ushort(lx) | ((uint32_t)__bfloat16_as_ushort(ly) << 16);
}

// ---------------- prep: feature transpose NCHW fp32 -> NHWC bf16 ----------------
__global__ void tposef_kernel(const float* __restrict__ in, int C, int H, int W, int outOff) {
    __shared__ float tile[32][33];
    int nz = blockIdx.z;
    int n = nz / H, y = nz % H;
    int x0 = blockIdx.x * 32, c0 = blockIdx.y * 32;
    int tx = threadIdx.x, ty = threadIdx.y;
#pragma unroll
    for (int k = 0; k < 4; k++) {
        int c = c0 + ty + 8 * k, x = x0 + tx;
        if (c < C && x < W)
            tile[ty + 8 * k][tx] = in[((size_t)(n * C + c) * H + y) * W + x];
    }
    __syncthreads();
#pragma unroll
    for (int k = 0; k < 4; k++) {
        int x = x0 + ty + 8 * k, c = c0 + tx;
        if (c < C && x < W)
            d_fTb[outOff + ((size_t)(n * H + y) * W + x) * C + c] =
                __float2bfloat16(tile[tx][ty + 8 * k]);
    }
}

// ---------------- prep: sampling B in mma fragment layout ----------------
__global__ void wbfprep_kernel(const float* __restrict__ we0, const float* __restrict__ we1,
                               const float* __restrict__ we2, const float* __restrict__ we3) {
    int e = blockIdx.x * 256 + threadIdx.x;
    if (e >= 45 * 8 * 32 * 4) return;
    int q = e & 3, lane = (e >> 2) & 31, np = (e >> 7) & 7, c = e >> 10;
    int t = q >> 1, reg = q & 1;
    int n = (np * 2 + t) * 8 + (lane >> 2);
    int k = c * 16 + reg * 8 + 2 * (lane & 3);
    uint32_t out = 0;
#pragma unroll
    for (int h = 0; h < 2; h++) {
        int ch = k + h;
        float v;
        if (ch < 48)       v = we0[n * 48 + ch];
        else if (ch < 144) v = we1[n * 96 + (ch - 48)];
        else if (ch < 336) v = we2[n * 192 + (ch - 144)];
        else               v = we3[n * 384 + (ch - 336)];
        __nv_bfloat16 b = __float2bfloat16(v);
        out |= (uint32_t)__bfloat16_as_ushort(b) << (16 * h);
    }
    d_wBf[e] = out;
}

// ---------------- prep: conv W hi/lo fragments ----------------
__global__ void wcfprep_kernel(const float* __restrict__ cw) {
    int e = blockIdx.x * 256 + threadIdx.x;
    if (e >= 72 * 8 * 32 * 4) return;
    int q = e & 3, lane = (e >> 2) & 31, np = (e >> 7) & 7, kc = e >> 10;
    int t = q >> 1, reg = q & 1;
    int n = (np * 2 + t) * 8 + (lane >> 2);
    int kf = kc * 16 + reg * 8 + 2 * (lane & 3);
    uint32_t oh = 0, ol = 0;
#pragma unroll
    for (int h = 0; h < 2; h++) {
        int kfe = kf + h;
        int k = kfe >> 7, c = kfe & 127;
        float v = cw[((size_t)n * 128 + c) * 9 + k];
        __nv_bfloat16 bh = __float2bfloat16_rn(v);
        float r = v - __bfloat162float(bh);
        __nv_bfloat16 bl = __float2bfloat16_rn(r);
        oh |= (uint32_t)__bfloat16_as_ushort(bh) << (16 * h);
        ol |= (uint32_t)__bfloat16_as_ushort(bl) << (16 * h);
    }
    d_cwh[e] = oh;
    d_cwl[e] = ol;
}

__global__ void bsum_kernel(const float* __restrict__ be0, const float* __restrict__ be1,
                            const float* __restrict__ be2, const float* __restrict__ be3) {
    int o = threadIdx.x;
    d_bsum[o] = 0.025f * (be0[o] + be1[o] + be2[o] + be3[o]);
}

// ---------------- sampling positions ----------------
__device__ __forceinline__ float dot4(float4 a, float4 b) {
    return a.x * b.x + a.y * b.y + a.z * b.z + a.w * b.w;
}

__global__ void pos_kernel(const float* __restrict__ query, const float* __restrict__ key,
                           const float* __restrict__ value,
                           const float* __restrict__ w_off, const float* __restrict__ b_off,
                           const float* __restrict__ w_attn, const float* __restrict__ b_attn,
                           float* __restrict__ spo) {
    int w = blockIdx.x * 8 + (threadIdx.x >> 5);
    if (w >= NPTS) return;
    int lane = threadIdx.x & 31;

    const float4* q4 = (const float4*)query;
    const float4* wo4 = (const float4*)w_off;
    float4 qv = q4[(size_t)w * 32 + lane];
    float d0 = dot4(qv, wo4[lane]);
    float d1 = dot4(qv, wo4[32 + lane]);

    int bt1 = w / PK;
    int p = (w % PK) % PP;
    const float4* v4 = (const float4*)value;
    const float4* wa4 = (const float4*)w_attn;
    float4 vv = v4[((size_t)bt1 * PP + p) * 32 + lane];
    float e0 = dot4(vv, wa4[lane]);
    float e1 = dot4(vv, wa4[32 + lane]);

#pragma unroll
    for (int s = 16; s; s >>= 1) {
        d0 += __shfl_xor_sync(0xFFFFFFFFu, d0, s);
        d1 += __shfl_xor_sync(0xFFFFFFFFu, d1, s);
        e0 += __shfl_xor_sync(0xFFFFFFFFu, e0, s);
        e1 += __shfl_xor_sync(0xFFFFFFFFu, e1, s);
    }
    if (lane == 0) {
        float o0 = tanhf(d0 + b_off[0]);
        float o1 = tanhf(d1 + b_off[1]);
        float l0 = e0 + b_attn[0], l1 = e1 + b_attn[1];
        float m = fmaxf(l0, l1);
        float x0 = expf(l0 - m), x1 = expf(l1 - m);
        float inv = 1.0f / (x0 + x1);
        spo[2 * w]     = key[2 * w]     + o0 * (x0 * inv);
        spo[2 * w + 1] = key[2 * w + 1] + o1 * (x1 * inv);
    }
}

// ---------------- bilinear geometry ----------------
__device__ __forceinline__ void geomcalc(bool valid, float gx, float gy, int n, int lvl,
                                         int4& o, float4& wv) {
    const int Hs[4] = {96, 48, 24, 12};
    const int Ws[4] = {72, 36, 18, 9};
    const int Cs[4] = {48, 96, 192, 384};
    const int FO[4] = {FT_OFF0, FT_OFF1, FT_OFF2, FT_OFF3};
    o = make_int4(0, 0, 0, 0);
    wv = make_float4(0.f, 0.f, 0.f, 0.f);
    if (!valid) return;
    int H = Hs[lvl], W = Ws[lvl], C = Cs[lvl];
    float ix = ((gx + 1.f) * (float)W - 1.f) * 0.5f;
    float iy = ((gy + 1.f) * (float)H - 1.f) * 0.5f;
    float fx = floorf(ix), fy = floorf(iy);
    int x0 = (int)fx, y0 = (int)fy;
    float wx1 = ix - fx, wy1 = iy - fy;
    float wx0 = 1.f - wx1, wy0 = 1.f - wy1;
    int base = FO[lvl] + n * (H * W * C);
    bool vx0 = (unsigned)x0 < (unsigned)W;
    bool vx1 = (unsigned)(x0 + 1) < (unsigned)W;
    bool vy0 = (unsigned)y0 < (unsigned)H;
    bool vy1 = (unsigned)(y0 + 1) < (unsigned)H;
    int r0 = y0 * W, r1 = r0 + W;
    if (vy0 && vx0) { o.x = base + (r0 + x0) * C;     wv.x = wy0 * wx0; }
    if (vy0 && vx1) { o.y = base + (r0 + x0 + 1) * C; wv.y = wy0 * wx1; }
    if (vy1 && vx0) { o.z = base + (r1 + x0) * C;     wv.z = wy1 * wx0; }
    if (vy1 && vx1) { o.w = base + (r1 + x0 + 1) * C; wv.w = wy1 * wx1; }
}

// ---------------- gather: 2 threads/point, thread h owns channel half h ----------------
// Each thread loads 4 corners x 16B (8 channels, LDG.128) and does the FULL
// 4-corner bilinear for its half locally. No shfl. 8 LDG.128 / point-chunk.
__device__ __forceinline__ void gather_load3(int cn, int tid, const int4* goff,
                                             const uint4* fp4, uint4 ca[4], int& cidx) {
    int h = tid & 1, pt = tid >> 1;
    int ch0 = cn * 16;
    int lvl = (ch0 < 48) ? 0 : (ch0 < 144) ? 1 : (ch0 < 336) ? 2 : 3;
    int gb  = (lvl == 0) ? 0 : (lvl == 1) ? 48 : (lvl == 2) ? 144 : 336;
    int chl = ch0 - gb + h * 8;       // element offset, multiple of 8 (16B aligned)
    cidx = lvl * 128 + pt;
    int4 o = goff[cidx];
    ca[0] = fp4[(o.x + chl) >> 3];
    ca[1] = fp4[(o.y + chl) >> 3];
    ca[2] = fp4[(o.z + chl) >> 3];
    ca[3] = fp4[(o.w + chl) >> 3];
}

__device__ __forceinline__ void gather_store3(int tid, const float4* gwv,
                                              uint4 ca[4], int cidx,
                                              unsigned char* abuf) {
    int h = tid & 1, pt = tid >> 1;
    float4 wv = gwv[cidx];
    uint32_t w00, w01, w10, w11;
    CVT_BF16X2_BCAST(w00, wv.x);
    CVT_BF16X2_BCAST(w01, wv.y);
    CVT_BF16X2_BCAST(w10, wv.z);
    CVT_BF16X2_BCAST(w11, wv.w);
    const uint32_t* c0 = (const uint32_t*)&ca[0];
    const uint32_t* c1 = (const uint32_t*)&ca[1];
    const uint32_t* c2 = (const uint32_t*)&ca[2];
    const uint32_t* c3 = (const uint32_t*)&ca[3];
    uint32_t out[4];
#pragma unroll
    for (int j = 0; j < 4; j++) {
        uint32_t t = 0;
        FMA_BF16X2(t, c0[j], w00, t);
        FMA_BF16X2(t, c1[j], w01, t);
        FMA_BF16X2(t, c2[j], w10, t);
        FMA_BF16X2(t, c3[j], w11, t);
        out[j] = t;
    }
    *(uint4*)(abuf + pt * ASTRIDE + h * 16) =
        make_uint4(out[0], out[1], out[2], out[3]);
}

// ---------------- main: mma.sync bf16 GEMM, R10 skeleton + LDG.128 gather ----------------
__global__ void __launch_bounds__(256) main3_kernel(
    const float* __restrict__ sp, const float* __restrict__ query,
    float* __restrict__ outq) {
    __shared__ __align__(16) unsigned char abuf[2][128 * ASTRIDE];
    __shared__ int4 goff[512];
    __shared__ float4 gwv[512];

    int tid = threadIdx.x;
    int lane = tid & 31, wid = tid >> 5;
    int warp_m = wid & 3, warp_n = wid >> 2;
    int qb = blockIdx.x * 128;

#pragma unroll
    for (int s = 0; s < 2; s++) {
        int task = s * 256 + tid;
        int lvl = task >> 7, pt = task & 127;
        int q = qb + pt;
        bool valid = q < NPTS;
        float gx = 0.f, gy = 0.f;
        int n = 0;
        if (valid) {
            gx = sp[2 * q];
            gy = sp[2 * q + 1];
            n = q / 4131;
        }
        int4 o; float4 wv;
        geomcalc(valid, gx, gy, n, lvl, o, wv);
        goff[task] = o;
        gwv[task] = wv;
    }
    __syncthreads();

    float d[2][8][4];
#pragma unroll
    for (int i = 0; i < 2; i++)
#pragma unroll
        for (int j = 0; j < 8; j++)
#pragma unroll
            for (int k = 0; k < 4; k++) d[i][j][k] = 0.f;

    const uint4* fp4 = (const uint4*)d_fTb;
    const uint4* wB4 = (const uint4*)d_wBf;
    uint32_t abase = smem_to_u32(abuf);

    uint4 ca[4];
    int cidx;
    uint4 bcur[4], bnext[4];

    gather_load3(0, tid, goff, fp4, ca, cidx);
#pragma unroll
    for (int i = 0; i < 4; i++)
        bcur[i] = wB4[(warp_n * 4 + i) * 32 + lane];
    gather_store3(tid, gwv, ca, cidx, abuf[0]);
    __syncthreads();

#pragma unroll 1
    for (int c = 0; c < NCH; c++) {
        bool more = (c + 1) < NCH;
        if (more) {
            gather_load3(c + 1, tid, goff, fp4, ca, cidx);
#pragma unroll
            for (int i = 0; i < 4; i++)
                bnext[i] = wB4[((c + 1) * 8 + warp_n * 4 + i) * 32 + lane];
        }

        uint32_t a[2][4];
        uint32_t ab = abase + (c & 1) * (128 * ASTRIDE) +
                      (warp_m * 32 + (lane & 15)) * ASTRIDE + (lane >> 4) * 16;
        ldsm_x4(a[0], ab);
        ldsm_x4(a[1], ab + 16 * ASTRIDE);
#pragma unroll
        for (int nt = 0; nt < 8; nt++) {
            uint32_t b0 = (nt & 1) ? bcur[nt >> 1].z : bcur[nt >> 1].x;
            uint32_t b1 = (nt & 1) ? bcur[nt >> 1].w : bcur[nt >> 1].y;
            mma16816(d[0][nt], a[0], b0, b1);
            mma16816(d[1][nt], a[1], b0, b1);
        }

        if (more) {
            gather_store3(tid, gwv, ca, cidx, abuf[(c + 1) & 1]);
#pragma unroll
            for (int i = 0; i < 4; i++) bcur[i] = bnext[i];
        }
        __syncthreads();
    }

    // ---- epilogue: blend + store fp32 + hi/lo bf16 for the conv GEMM ----
#pragma unroll
    for (int mt = 0; mt < 2; mt++) {
#pragma unroll
        for (int rr = 0; rr < 2; rr++) {
            int q = qb + warp_m * 32 + mt * 16 + rr * 8 + (lane >> 2);
            if (q < NPTS) {
#pragma unroll
                for (int nt = 0; nt < 8; nt++) {
                    int o = warp_n * 64 + nt * 8 + 2 * (lane & 3);
                    float2 qv = *(const float2*)&query[(size_t)q * 128 + o];
                    float2 bsv = *(const float2*)&d_bsum[o];
                    float2 r;
                    r.x = 0.025f * d[mt][nt][rr * 2 + 0] + bsv.x + 0.9f * qv.x;
                    r.y = 0.025f * d[mt][nt][rr * 2 + 1] + bsv.y + 0.9f * qv.y;
                    *(float2*)&outq[(size_t)q * 128 + o] = r;
                    uint32_t hi = pack_hi(r.x, r.y);
                    uint32_t lo = pack_lo(r.x, r.y, hi);
                    int ui = q * 64 + (o >> 1);
                    d_nqh[ui] = hi;
                    d_nql[ui] = lo;
                }
            }
        }
    }
}

// ---------------- conv as split-precision bf16 GEMM ----------------
__global__ void __launch_bounds__(256) conv2_kernel(const float* __restrict__ conv_b,
                                                    float* __restrict__ nv) {
    __shared__ __align__(16) unsigned char ah[64 * 128];
    __shared__ __align__(16) unsigned char al[64 * 128];

    int tid = threadIdx.x;
    int lane = tid & 31, wid = tid >> 5;
    int warp_m = wid & 1, warp_n = wid >> 1;
    int m0 = blockIdx.x * 64;

    float d[2][4][4];
#pragma unroll
    for (int i = 0; i < 2; i++)
#pragma unroll
        for (int j = 0; j < 4; j++)
#pragma unroll
            for (int k = 0; k < 4; k++) d[i][j][k] = 0.f;

    const uint4* nqh4 = (const uint4*)d_nqh;
    const uint4* nql4 = (const uint4*)d_nql;
    const uint4* cwh4 = (const uint4*)d_cwh;
    const uint4* cwl4 = (const uint4*)d_cwl;
    uint32_t ahb = smem_to_u32(ah);
    uint32_t alb = smem_to_u32(al);

#pragma unroll 1
    for (int it = 0; it < 18; it++) {
        __syncthreads();
#pragma unroll
        for (int j = 0; j < 2; j++) {
            int idx = tid * 2 + j;
            int row = idx >> 3, cu = idx & 7;
            int m = m0 + row;
            int mc = (m < MROWS) ? m : MROWS - 1;
            int g = mc * 144 + it * 8 + cu;
            int soff = row * 128 + ((cu ^ (row & 7)) * 16);
            *(uint4*)(ah + soff) = nqh4[g];
            *(uint4*)(al + soff) = nql4[g];
        }
        __syncthreads();

#pragma unroll
        for (int kt = 0; kt < 4; kt++) {
            int kc = it * 4 + kt;
            uint4 bh0 = cwh4[((kc * 8) + 2 * warp_n + 0) * 32 + lane];
            uint4 bh1 = cwh4[((kc * 8) + 2 * warp_n + 1) * 32 + lane];
            uint4 bl0 = cwl4[((kc * 8) + 2 * warp_n + 0) * 32 + lane];
            uint4 bl1 = cwl4[((kc * 8) + 2 * warp_n + 1) * 32 + lane];
            uint32_t a_h[2][4], a_l[2][4];
#pragma unroll
            for (int mt = 0; mt < 2; mt++) {
                int row = warp_m * 32 + mt * 16 + (lane & 15);
                int cu = kt * 2 + (lane >> 4);
                uint32_t addr = row * 128 + ((cu ^ (row & 7)) * 16);
                ldsm_x4(a_h[mt], ahb + addr);
                ldsm_x4(a_l[mt], alb + addr);
            }
#pragma unroll
            for (int mt = 0; mt < 2; mt++) {
#pragma unroll
                for (int nt = 0; nt < 4; nt++) {
                    uint4 bh = (nt >> 1) ? bh1 : bh0;
                    uint4 bl = (nt >> 1) ? bl1 : bl0;
                    uint32_t bh_0 = (nt & 1) ? bh.z : bh.x;
                    uint32_t bh_1 = (nt & 1) ? bh.w : bh.y;
                    uint32_t bl_0 = (nt & 1) ? bl.z : bl.x;
                    uint32_t bl_1 = (nt & 1) ? bl.w : bl.y;
                    mma16816(d[mt][nt], a_h[mt], bh_0, bh_1);
                    mma16816(d[mt][nt], a_h[mt], bl_0, bl_1);
                    mma16816(d[mt][nt], a_l[mt], bh_0, bh_1);
                }
            }
        }
    }

#pragma unroll
    for (int mt = 0; mt < 2; mt++) {
#pragma unroll
        for (int rr = 0; rr < 2; rr++) {
            int m = m0 + warp_m * 32 + mt * 16 + rr * 8 + (lane >> 2);
            if (m < MROWS) {
#pragma unroll
                for (int nt = 0; nt < 4; nt++) {
                    int o = warp_n * 32 + nt * 8 + 2 * (lane & 3);
                    float2 cb = *(const float2*)&conv_b[o];
                    float2 r;
                    r.x = d[mt][nt][rr * 2 + 0] + cb.x;
                    r.y = d[mt][nt][rr * 2 + 1] + cb.y;
                    *(float2*)&nv[(size_t)m * 128 + o] = r;
                }
            }
        }
    }
}

// ---------------- launch ----------------
extern "C" void kernel_launch(void* const* d_in, const int* in_sizes, int n_in,
                              void* d_out, int out_size) {
    const float* f0     = (const float*)d_in[0];
    const float* f1     = (const float*)d_in[1];
    const float* f2     = (const float*)d_in[2];
    const float* f3     = (const float*)d_in[3];
    const float* query  = (const float*)d_in[4];
    const float* key    = (const float*)d_in[5];
    const float* value  = (const float*)d_in[6];
    const float* w_off  = (const float*)d_in[7];
    const float* b_off  = (const float*)d_in[8];
    const float* w_attn = (const float*)d_in[9];
    const float* b_attn = (const float*)d_in[10];
    const float* we0    = (const float*)d_in[11];
    const float* be0    = (const float*)d_in[12];
    const float* we1    = (const float*)d_in[13];
    const float* be1    = (const float*)d_in[14];
    const float* we2    = (const float*)d_in[15];
    const float* be2    = (const float*)d_in[16];
    const float* we3    = (const float*)d_in[17];
    const float* be3    = (const float*)d_in[18];
    const float* conv_w = (const float*)d_in[19];
    const float* conv_b = (const float*)d_in[20];

    float* out   = (float*)d_out;
    float* outQ  = out + OUT_Q_OFF;
    float* outV  = out + OUT_V_OFF;
    float* outSP = out + OUT_SP_OFF;

    dim3 tb(32, 8);
    tposef_kernel<<<dim3(3, 2, 18 * 96), tb>>>(f0, 48, 96, 72, FT_OFF0);
    tposef_kernel<<<dim3(2, 3, 18 * 48), tb>>>(f1, 96, 48, 36, FT_OFF1);
    tposef_kernel<<<dim3(1, 6, 18 * 24), tb>>>(f2, 192, 24, 18, FT_OFF2);
    tposef_kernel<<<dim3(1, 12, 18 * 12), tb>>>(f3, 384, 12, 9, FT_OFF3);

    wbfprep_kernel<<<180, 256>>>(we0, we1, we2, we3);
    wcfprep_kernel<<<288, 256>>>(conv_w);
    bsum_kernel<<<1, 128>>>(be0, be1, be2, be3);

    pos_kernel<<<9295, 256>>>(query, key, value, w_off, b_off, w_attn, b_attn, outSP);

    main3_kernel<<<(NPTS + 127) / 128, 256>>>(outSP, query, outQ);

    conv2_kernel<<<(MROWS + 63) / 64, 256>>>(conv_b, outV);
}

// round 15
// speedup vs baseline: 1.1824x; 1.0249x over previous
#include <cuda_runtime.h>
#include <cuda_bf16.h>
#include <math.h>
#include <stdint.h>

// ---------------- problem constants ----------------
#define NPTS   74358      // 2 * 243 * 153
#define PK     153
#define PP     17
#define CC     128
#define MROWS  8262       // conv GEMM rows = 486*17

// feature levels: C_l = {48,96,192,384}, H = {96,48,24,12}, W = {72,36,18,9}
#define FT_OFF0 0
#define FT_OFF1 5971968
#define FT_OFF2 8957952
#define FT_OFF3 10450944
#define FT_TOTAL 11197440

// output regions (floats)
#define OUT_Q_OFF  0
#define OUT_V_OFF  9517824
#define OUT_SP_OFF 10575360

#define NCH     45          // K chunks of 16 channels; level edges at chunks 3/9/21
#define ASTRIDE 48          // bytes per point-row in A smem (24 bf16)

// fused tposef block ranges
#define TPB0 10368          // L0: 3 xt * 2 ct * 18*96
#define TPB1 15552          // +L1: 2 * 3 * 18*48 = 5184
#define TPB2 18144          // +L2: 1 * 6 * 18*24 = 2592
#define TPB3 20736          // +L3: 1 * 12 * 18*12 = 2592

// ---------------- device scratch ----------------
__device__ __nv_bfloat16 d_fTb[FT_TOTAL];                  // bf16 NHWC feature maps
__device__ __align__(16) uint32_t d_wBf[45 * 8 * 32 * 4];  // sampling B frags
__device__ float d_bsum[128];                              // 0.025 * sum(be_l)
__device__ float d_aw[MROWS * 2];                          // softmax attn per (b,t1,p)
__device__ __align__(16) uint32_t d_nqh[4758912];          // new_query hi bf16 pairs
__device__ __align__(16) uint32_t d_nql[4758912];          // new_query lo bf16 pairs
__device__ __align__(16) uint32_t d_cwh[72 * 8 * 32 * 4];  // conv W hi frags
__device__ __align__(16) uint32_t d_cwl[72 * 8 * 32 * 4];  // conv W lo frags

// ---------------- helpers ----------------
__device__ __forceinline__ uint32_t smem_to_u32(const void* p) {
    uint32_t a;
    asm("{ .reg .u64 t; cvta.to.shared.u64 t, %1; cvt.u32.u64 %0, t; }" : "=r"(a) : "l"(p));
    return a;
}
__device__ __forceinline__ void ldsm_x4(uint32_t* a, uint32_t saddr) {
    asm volatile("ldmatrix.sync.aligned.m8n8.x4.shared.b16 {%0,%1,%2,%3}, [%4];"
                 : "=r"(a[0]), "=r"(a[1]), "=r"(a[2]), "=r"(a[3]) : "r"(saddr));
}
__device__ __forceinline__ void mma16816(float* d, const uint32_t* a, uint32_t b0, uint32_t b1) {
    asm volatile(
        "mma.sync.aligned.m16n8k16.row.col.f32.bf16.bf16.f32 "
        "{%0,%1,%2,%3}, {%4,%5,%6,%7}, {%8,%9}, {%0,%1,%2,%3};"
        : "+f"(d[0]), "+f"(d[1]), "+f"(d[2]), "+f"(d[3])
        : "r"(a[0]), "r"(a[1]), "r"(a[2]), "r"(a[3]), "r"(b0), "r"(b1));
}
#define FMA_BF16X2(r, a, b, c) \
    asm("fma.rn.bf16x2 %0, %1, %2, %3;" : "=r"(r) : "r"(a), "r"(b), "r"(c))
#define CVT_BF16X2_BCAST(r, f) \
    asm("cvt.rn.bf16x2.f32 %0, %1, %2;" : "=r"(r) : "f"(f), "f"(f))

__device__ __forceinline__ uint32_t pack_hi(float x, float y) {
    __nv_bfloat16 hx = __float2bfloat16_rn(x);
    __nv_bfloat16 hy = __float2bfloat16_rn(y);
    return (uint32_t)__bfloat16_as_ushort(hx) | ((uint32_t)__bfloat16_as_ushort(hy) << 16);
}
__device__ __forceinline__ uint32_t pack_lo(float x, float y, uint32_t hi) {
    float hx = __bfloat162float(__ushort_as_bfloat16((unsigned short)(hi & 0xFFFF)));
    float hy = __bfloat162float(__ushort_as_bfloat16((unsigned short)(hi >> 16)));
    __nv_bfloat16 lx = __float2bfloat16_rn(x - hx);
    __nv_bfloat16 ly = __float2bfloat16_rn(y - hy);
    return (uint32_t)__bfloat16_as_ushort(lx) | ((uint32_t)__bfloat16_as_ushort(ly) << 16);
}

// ---------------- prep: fused feature transpose NCHW fp32 -> NHWC bf16 ----------------
__global__ void tposefz_kernel(const float* __restrict__ f0, const float* __restrict__ f1,
                               const float* __restrict__ f2, const float* __restrict__ f3) {
    __shared__ float tile[32][33];
    int b = blockIdx.x;
    const float* in;
    int C, H, W, outOff, xb, cb, nz;
    if (b < TPB0) {
        in = f0; C = 48; H = 96; W = 72; outOff = FT_OFF0;
        int r = b; xb = r % 3; r /= 3; cb = r % 2; nz = r / 2;
    } else if (b < TPB1) {
        in = f1; C = 96; H = 48; W = 36; outOff = FT_OFF1;
        int r = b - TPB0; xb = r % 2; r /= 2; cb = r % 3; nz = r / 3;
    } else if (b < TPB2) {
        in = f2; C = 192; H = 24; W = 18; outOff = FT_OFF2;
        int r = b - TPB1; xb = 0; cb = r % 6; nz = r / 6;
    } else {
        in = f3; C = 384; H = 12; W = 9; outOff = FT_OFF3;
        int r = b - TPB2; xb = 0; cb = r % 12; nz = r / 12;
    }
    int n = nz / H, y = nz % H;
    int x0 = xb * 32, c0 = cb * 32;
    int tx = threadIdx.x, ty = threadIdx.y;
#pragma unroll
    for (int k = 0; k < 4; k++) {
        int c = c0 + ty + 8 * k, x = x0 + tx;
        if (c < C && x < W)
            tile[ty + 8 * k][tx] = in[((size_t)(n * C + c) * H + y) * W + x];
    }
    __syncthreads();
#pragma unroll
    for (int k = 0; k < 4; k++) {
        int x = x0 + ty + 8 * k, c = c0 + tx;
        if (c < C && x < W)
            d_fTb[outOff + ((size_t)(n * H + y) * W + x) * C + c] =
                __float2bfloat16(tile[tx][ty + 8 * k]);
    }
}

// ---------------- prep: sampling B frags + folded bsum ----------------
__global__ void wbfprep_kernel(const float* __restrict__ we0, const float* __restrict__ we1,
                               const float* __restrict__ we2, const float* __restrict__ we3,
                               const float* __restrict__ be0, const float* __restrict__ be1,
                               const float* __restrict__ be2, const float* __restrict__ be3) {
    int e = blockIdx.x * 256 + threadIdx.x;
    if (blockIdx.x == 0 && threadIdx.x < 128) {
        int o = threadIdx.x;
        d_bsum[o] = 0.025f * (be0[o] + be1[o] + be2[o] + be3[o]);
    }
    if (e >= 45 * 8 * 32 * 4) return;
    int q = e & 3, lane = (e >> 2) & 31, np = (e >> 7) & 7, c = e >> 10;
    int t = q >> 1, reg = q & 1;
    int n = (np * 2 + t) * 8 + (lane >> 2);
    int k = c * 16 + reg * 8 + 2 * (lane & 3);
    uint32_t out = 0;
#pragma unroll
    for (int h = 0; h < 2; h++) {
        int ch = k + h;
        float v;
        if (ch < 48)       v = we0[n * 48 + ch];
        else if (ch < 144) v = we1[n * 96 + (ch - 48)];
        else if (ch < 336) v = we2[n * 192 + (ch - 144)];
        else               v = we3[n * 384 + (ch - 336)];
        __nv_bfloat16 b = __float2bfloat16(v);
        out |= (uint32_t)__bfloat16_as_ushort(b) << (16 * h);
    }
    d_wBf[e] = out;
}

// ---------------- prep: conv W hi/lo fragments ----------------
__global__ void wcfprep_kernel(const float* __restrict__ cw) {
    int e = blockIdx.x * 256 + threadIdx.x;
    if (e >= 72 * 8 * 32 * 4) return;
    int q = e & 3, lane = (e >> 2) & 31, np = (e >> 7) & 7, kc = e >> 10;
    int t = q >> 1, reg = q & 1;
    int n = (np * 2 + t) * 8 + (lane >> 2);
    int kf = kc * 16 + reg * 8 + 2 * (lane & 3);
    uint32_t oh = 0, ol = 0;
#pragma unroll
    for (int h = 0; h < 2; h++) {
        int kfe = kf + h;
        int k = kfe >> 7, c = kfe & 127;
        float v = cw[((size_t)n * 128 + c) * 9 + k];
        __nv_bfloat16 bh = __float2bfloat16_rn(v);
        float r = v - __bfloat162float(bh);
        __nv_bfloat16 bl = __float2bfloat16_rn(r);
        oh |= (uint32_t)__bfloat16_as_ushort(bh) << (16 * h);
        ol |= (uint32_t)__bfloat16_as_ushort(bl) << (16 * h);
    }
    d_cwh[e] = oh;
    d_cwl[e] = ol;
}

// ---------------- attention softmax: one row per (b,t1,p), computed once ----------------
__device__ __forceinline__ float dot4(float4 a, float4 b) {
    return a.x * b.x + a.y * b.y + a.z * b.z + a.w * b.w;
}

__global__ void aw_kernel(const float* __restrict__ value,
                          const float* __restrict__ w_attn, const float* __restrict__ b_attn) {
    int w = blockIdx.x * 8 + (threadIdx.x >> 5);
    if (w >= MROWS) return;
    int lane = threadIdx.x & 31;
    const float4* v4 = (const float4*)value;
    const float4* wa4 = (const float4*)w_attn;
    float4 vv = v4[(size_t)w * 32 + lane];
    float e0 = dot4(vv, wa4[lane]);
    float e1 = dot4(vv, wa4[32 + lane]);
#pragma unroll
    for (int s = 16; s; s >>= 1) {
        e0 += __shfl_xor_sync(0xFFFFFFFFu, e0, s);
        e1 += __shfl_xor_sync(0xFFFFFFFFu, e1, s);
    }
    if (lane == 0) {
        float l0 = e0 + b_attn[0], l1 = e1 + b_attn[1];
        float m = fmaxf(l0, l1);
        float x0 = expf(l0 - m), x1 = expf(l1 - m);
        float inv = 1.0f / (x0 + x1);
        d_aw[2 * w] = x0 * inv;
        d_aw[2 * w + 1] = x1 * inv;
    }
}

// ---------------- sampling positions (uses precomputed aw) ----------------
__global__ void pos_kernel(const float* __restrict__ query, const float* __restrict__ key,
                           const float* __restrict__ w_off, const float* __restrict__ b_off,
                           float* __restrict__ spo) {
    int w = blockIdx.x * 8 + (threadIdx.x >> 5);
    if (w >= NPTS) return;
    int lane = threadIdx.x & 31;

    const float4* q4 = (const float4*)query;
    const float4* wo4 = (const float4*)w_off;
    float4 qv = q4[(size_t)w * 32 + lane];
    float d0 = dot4(qv, wo4[lane]);
    float d1 = dot4(qv, wo4[32 + lane]);

#pragma unroll
    for (int s = 16; s; s >>= 1) {
        d0 += __shfl_xor_sync(0xFFFFFFFFu, d0, s);
        d1 += __shfl_xor_sync(0xFFFFFFFFu, d1, s);
    }
    if (lane == 0) {
        float o0 = tanhf(d0 + b_off[0]);
        float o1 = tanhf(d1 + b_off[1]);
        int bt1 = w / PK;
        int p = (w % PK) % PP;
        int ai = bt1 * PP + p;
        spo[2 * w]     = key[2 * w]     + o0 * d_aw[2 * ai];
        spo[2 * w + 1] = key[2 * w + 1] + o1 * d_aw[2 * ai + 1];
    }
}

// ---------------- bilinear geometry ----------------
__device__ __forceinline__ void geomcalc(bool valid, float gx, float gy, int n, int lvl,
                                         int4& o, float4& wv) {
    const int Hs[4] = {96, 48, 24, 12};
    const int Ws[4] = {72, 36, 18, 9};
    const int Cs[4] = {48, 96, 192, 384};
    const int FO[4] = {FT_OFF0, FT_OFF1, FT_OFF2, FT_OFF3};
    o = make_int4(0, 0, 0, 0);
    wv = make_float4(0.f, 0.f, 0.f, 0.f);
    if (!valid) return;
    int H = Hs[lvl], W = Ws[lvl], C = Cs[lvl];
    float ix = ((gx + 1.f) * (float)W - 1.f) * 0.5f;
    float iy = ((gy + 1.f) * (float)H - 1.f) * 0.5f;
    float fx = floorf(ix), fy = floorf(iy);
    int x0 = (int)fx, y0 = (int)fy;
    float wx1 = ix - fx, wy1 = iy - fy;
    float wx0 = 1.f - wx1, wy0 = 1.f - wy1;
    int base = FO[lvl] + n * (H * W * C);
    bool vx0 = (unsigned)x0 < (unsigned)W;
    bool vx1 = (unsigned)(x0 + 1) < (unsigned)W;
    bool vy0 = (unsigned)y0 < (unsigned)H;
    bool vy1 = (unsigned)(y0 + 1) < (unsigned)H;
    int r0 = y0 * W, r1 = r0 + W;
    if (vy0 && vx0) { o.x = base + (r0 + x0) * C;     wv.x = wy0 * wx0; }
    if (vy0 && vx1) { o.y = base + (r0 + x0 + 1) * C; wv.y = wy0 * wx1; }
    if (vy1 && vx0) { o.z = base + (r1 + x0) * C;     wv.z = wy1 * wx0; }
    if (vy1 && vx1) { o.w = base + (r1 + x0 + 1) * C; wv.w = wy1 * wx1; }
}

// ---------------- gather: 2 threads/point, thread h owns channel half h ----------------
__device__ __forceinline__ void gather_load3(int cn, int tid, const int4* goff,
                                             const uint4* fp4, uint4 ca[4], int& cidx) {
    int h = tid & 1, pt = tid >> 1;
    int ch0 = cn * 16;
    int lvl = (ch0 < 48) ? 0 : (ch0 < 144) ? 1 : (ch0 < 336) ? 2 : 3;
    int gb  = (lvl == 0) ? 0 : (lvl == 1) ? 48 : (lvl == 2) ? 144 : 336;
    int chl = ch0 - gb + h * 8;
    cidx = lvl * 128 + pt;
    int4 o = goff[cidx];
    ca[0] = fp4[(o.x + chl) >> 3];
    ca[1] = fp4[(o.y + chl) >> 3];
    ca[2] = fp4[(o.z + chl) >> 3];
    ca[3] = fp4[(o.w + chl) >> 3];
}

__device__ __forceinline__ void gather_store3(int tid, const float4* gwv,
                                              uint4 ca[4], int cidx,
                                              unsigned char* abuf) {
    int h = tid & 1, pt = tid >> 1;
    float4 wv = gwv[cidx];
    uint32_t w00, w01, w10, w11;
    CVT_BF16X2_BCAST(w00, wv.x);
    CVT_BF16X2_BCAST(w01, wv.y);
    CVT_BF16X2_BCAST(w10, wv.z);
    CVT_BF16X2_BCAST(w11, wv.w);
    const uint32_t* c0 = (const uint32_t*)&ca[0];
    const uint32_t* c1 = (const uint32_t*)&ca[1];
    const uint32_t* c2 = (const uint32_t*)&ca[2];
    const uint32_t* c3 = (const uint32_t*)&ca[3];
    uint32_t out[4];
#pragma unroll
    for (int j = 0; j < 4; j++) {
        uint32_t t = 0;
        FMA_BF16X2(t, c0[j], w00, t);
        FMA_BF16X2(t, c1[j], w01, t);
        FMA_BF16X2(t, c2[j], w10, t);
        FMA_BF16X2(t, c3[j], w11, t);
        out[j] = t;
    }
    *(uint4*)(abuf + pt * ASTRIDE + h * 16) =
        make_uint4(out[0], out[1], out[2], out[3]);
}

// ---------------- main: mma.sync bf16 GEMM (R14, unchanged) ----------------
__global__ void __launch_bounds__(256) main3_kernel(
    const float* __restrict__ sp, const float* __restrict__ query,
    float* __restrict__ outq) {
    __shared__ __align__(16) unsigned char abuf[2][128 * ASTRIDE];
    __shared__ int4 goff[512];
    __shared__ float4 gwv[512];

    int tid = threadIdx.x;
    int lane = tid & 31, wid = tid >> 5;
    int warp_m = wid & 3, warp_n = wid >> 2;
    int qb = blockIdx.x * 128;

#pragma unroll
    for (int s = 0; s < 2; s++) {
        int task = s * 256 + tid;
        int lvl = task >> 7, pt = task & 127;
        int q = qb + pt;
        bool valid = q < NPTS;
        float gx = 0.f, gy = 0.f;
        int n = 0;
        if (valid) {
            gx = sp[2 * q];
            gy = sp[2 * q + 1];
            n = q / 4131;
        }
        int4 o; float4 wv;
        geomcalc(valid, gx, gy, n, lvl, o, wv);
        goff[task] = o;
        gwv[task] = wv;
    }
    __syncthreads();

    float d[2][8][4];
#pragma unroll
    for (int i = 0; i < 2; i++)
#pragma unroll
        for (int j = 0; j < 8; j++)
#pragma unroll
            for (int k = 0; k < 4; k++) d[i][j][k] = 0.f;

    const uint4* fp4 = (const uint4*)d_fTb;
    const uint4* wB4 = (const uint4*)d_wBf;
    uint32_t abase = smem_to_u32(abuf);

    uint4 ca[4];
    int cidx;
    uint4 bcur[4], bnext[4];

    gather_load3(0, tid, goff, fp4, ca, cidx);
#pragma unroll
    for (int i = 0; i < 4; i++)
        bcur[i] = wB4[(warp_n * 4 + i) * 32 + lane];
    gather_store3(tid, gwv, ca, cidx, abuf[0]);
    __syncthreads();

#pragma unroll 1
    for (int c = 0; c < NCH; c++) {
        bool more = (c + 1) < NCH;
        if (more) {
            gather_load3(c + 1, tid, goff, fp4, ca, cidx);
#pragma unroll
            for (int i = 0; i < 4; i++)
                bnext[i] = wB4[((c + 1) * 8 + warp_n * 4 + i) * 32 + lane];
        }

        uint32_t a[2][4];
        uint32_t ab = abase + (c & 1) * (128 * ASTRIDE) +
                      (warp_m * 32 + (lane & 15)) * ASTRIDE + (lane >> 4) * 16;
        ldsm_x4(a[0], ab);
        ldsm_x4(a[1], ab + 16 * ASTRIDE);
#pragma unroll
        for (int nt = 0; nt < 8; nt++) {
            uint32_t b0 = (nt & 1) ? bcur[nt >> 1].z : bcur[nt >> 1].x;
            uint32_t b1 = (nt & 1) ? bcur[nt >> 1].w : bcur[nt >> 1].y;
            mma16816(d[0][nt], a[0], b0, b1);
            mma16816(d[1][nt], a[1], b0, b1);
        }

        if (more) {
            gather_store3(tid, gwv, ca, cidx, abuf[(c + 1) & 1]);
#pragma unroll
            for (int i = 0; i < 4; i++) bcur[i] = bnext[i];
        }
        __syncthreads();
    }

    // ---- epilogue: blend + store fp32 + hi/lo bf16 for the conv GEMM ----
#pragma unroll
    for (int mt = 0; mt < 2; mt++) {
#pragma unroll
        for (int rr = 0; rr < 2; rr++) {
            int q = qb + warp_m * 32 + mt * 16 + rr * 8 + (lane >> 2);
            if (q < NPTS) {
#pragma unroll
                for (int nt = 0; nt < 8; nt++) {
                    int o = warp_n * 64 + nt * 8 + 2 * (lane & 3);
                    float2 qv = *(const float2*)&query[(size_t)q * 128 + o];
                    float2 bsv = *(const float2*)&d_bsum[o];
                    float2 r;
                    r.x = 0.025f * d[mt][nt][rr * 2 + 0] + bsv.x + 0.9f * qv.x;
                    r.y = 0.025f * d[mt][nt][rr * 2 + 1] + bsv.y + 0.9f * qv.y;
                    *(float2*)&outq[(size_t)q * 128 + o] = r;
                    uint32_t hi = pack_hi(r.x, r.y);
                    uint32_t lo = pack_lo(r.x, r.y, hi);
                    int ui = q * 64 + (o >> 1);
                    d_nqh[ui] = hi;
                    d_nql[ui] = lo;
                }
            }
        }
    }
}

// ---------------- conv as split-precision bf16 GEMM ----------------
__global__ void __launch_bounds__(256) conv2_kernel(const float* __restrict__ conv_b,
                                                    float* __restrict__ nv) {
    __shared__ __align__(16) unsigned char ah[64 * 128];
    __shared__ __align__(16) unsigned char al[64 * 128];

    int tid = threadIdx.x;
    int lane = tid & 31, wid = tid >> 5;
    int warp_m = wid & 1, warp_n = wid >> 1;
    int m0 = blockIdx.x * 64;

    float d[2][4][4];
#pragma unroll
    for (int i = 0; i < 2; i++)
#pragma unroll
        for (int j = 0; j < 4; j++)
#pragma unroll
            for (int k = 0; k < 4; k++) d[i][j][k] = 0.f;

    const uint4* nqh4 = (const uint4*)d_nqh;
    const uint4* nql4 = (const uint4*)d_nql;
    const uint4* cwh4 = (const uint4*)d_cwh;
    const uint4* cwl4 = (const uint4*)d_cwl;
    uint32_t ahb = smem_to_u32(ah);
    uint32_t alb = smem_to_u32(al);

#pragma unroll 1
    for (int it = 0; it < 18; it++) {
        __syncthreads();
#pragma unroll
        for (int j = 0; j < 2; j++) {
            int idx = tid * 2 + j;
            int row = idx >> 3, cu = idx & 7;
            int m = m0 + row;
            int mc = (m < MROWS) ? m : MROWS - 1;
            int g = mc * 144 + it * 8 + cu;
            int soff = row * 128 + ((cu ^ (row & 7)) * 16);
            *(uint4*)(ah + soff) = nqh4[g];
            *(uint4*)(al + soff) = nql4[g];
        }
        __syncthreads();

#pragma unroll
        for (int kt = 0; kt < 4; kt++) {
            int kc = it * 4 + kt;
            uint4 bh0 = cwh4[((kc * 8) + 2 * warp_n + 0) * 32 + lane];
            uint4 bh1 = cwh4[((kc * 8) + 2 * warp_n + 1) * 32 + lane];
            uint4 bl0 = cwl4[((kc * 8) + 2 * warp_n + 0) * 32 + lane];
            uint4 bl1 = cwl4[((kc * 8) + 2 * warp_n + 1) * 32 + lane];
            uint32_t a_h[2][4], a_l[2][4];
#pragma unroll
            for (int mt = 0; mt < 2; mt++) {
                int row = warp_m * 32 + mt * 16 + (lane & 15);
                int cu = kt * 2 + (lane >> 4);
                uint32_t addr = row * 128 + ((cu ^ (row & 7)) * 16);
                ldsm_x4(a_h[mt], ahb + addr);
                ldsm_x4(a_l[mt], alb + addr);
            }
#pragma unroll
            for (int mt = 0; mt < 2; mt++) {
#pragma unroll
                for (int nt = 0; nt < 4; nt++) {
                    uint4 bh = (nt >> 1) ? bh1 : bh0;
                    uint4 bl = (nt >> 1) ? bl1 : bl0;
                    uint32_t bh_0 = (nt & 1) ? bh.z : bh.x;
                    uint32_t bh_1 = (nt & 1) ? bh.w : bh.y;
                    uint32_t bl_0 = (nt & 1) ? bl.z : bl.x;
                    uint32_t bl_1 = (nt & 1) ? bl.w : bl.y;
                    mma16816(d[mt][nt], a_h[mt], bh_0, bh_1);
                    mma16816(d[mt][nt], a_h[mt], bl_0, bl_1);
                    mma16816(d[mt][nt], a_l[mt], bh_0, bh_1);
                }
            }
        }
    }

#pragma unroll
    for (int mt = 0; mt < 2; mt++) {
#pragma unroll
        for (int rr = 0; rr < 2; rr++) {
            int m = m0 + warp_m * 32 + mt * 16 + rr * 8 + (lane >> 2);
            if (m < MROWS) {
#pragma unroll
                for (int nt = 0; nt < 4; nt++) {
                    int o = warp_n * 32 + nt * 8 + 2 * (lane & 3);
                    float2 cb = *(const float2*)&conv_b[o];
                    float2 r;
                    r.x = d[mt][nt][rr * 2 + 0] + cb.x;
                    r.y = d[mt][nt][rr * 2 + 1] + cb.y;
                    *(float2*)&nv[(size_t)m * 128 + o] = r;
                }
            }
        }
    }
}

// ---------------- launch ----------------
extern "C" void kernel_launch(void* const* d_in, const int* in_sizes, int n_in,
                              void* d_out, int out_size) {
    const float* f0     = (const float*)d_in[0];
    const float* f1     = (const float*)d_in[1];
    const float* f2     = (const float*)d_in[2];
    const float* f3     = (const float*)d_in[3];
    const float* query  = (const float*)d_in[4];
    const float* key    = (const float*)d_in[5];
    const float* value  = (const float*)d_in[6];
    const float* w_off  = (const float*)d_in[7];
    const float* b_off  = (const float*)d_in[8];
    const float* w_attn = (const float*)d_in[9];
    const float* b_attn = (const float*)d_in[10];
    const float* we0    = (const float*)d_in[11];
    const float* be0    = (const float*)d_in[12];
    const float* we1    = (const float*)d_in[13];
    const float* be1    = (const float*)d_in[14];
    const float* we2    = (const float*)d_in[15];
    const float* be2    = (const float*)d_in[16];
    const float* we3    = (const float*)d_in[17];
    const float* be3    = (const float*)d_in[18];
    const float* conv_w = (const float*)d_in[19];
    const float* conv_b = (const float*)d_in[20];

    float* out   = (float*)d_out;
    float* outQ  = out + OUT_Q_OFF;
    float* outV  = out + OUT_V_OFF;
    float* outSP = out + OUT_SP_OFF;

    // launch order: main3 is launch #5 (0-based) so ncu -s 5 -c 1 captures it
    tposefz_kernel<<<TPB3, dim3(32, 8)>>>(f0, f1, f2, f3);                    // 0
    wbfprep_kernel<<<180, 256>>>(we0, we1, we2, we3, be0, be1, be2, be3);     // 1
    wcfprep_kernel<<<288, 256>>>(conv_w);                                     // 2
    aw_kernel<<<(MROWS + 7) / 8, 256>>>(value, w_attn, b_attn);               // 3
    pos_kernel<<<9295, 256>>>(query, key, w_off, b_off, outSP);               // 4
    main3_kernel<<<(NPTS + 127) / 128, 256>>>(outSP, query, outQ);            // 5
    conv2_kernel<<<(MROWS + 63) / 64, 256>>>(conv_b, outV);                   // 6
}

// round 16
// speedup vs baseline: 1.1916x; 1.0078x over previous
#include <cuda_runtime.h>
#include <cuda_bf16.h>
#include <math.h>
#include <stdint.h>

// ---------------- problem constants ----------------
#define NPTS   74358      // 2 * 243 * 153
#define PK     153
#define PP     17
#define CC     128
#define MROWS  8262       // conv GEMM rows = 486*17

// feature levels: C_l = {48,96,192,384}, H = {96,48,24,12}, W = {72,36,18,9}
#define FT_OFF0 0
#define FT_OFF1 5971968
#define FT_OFF2 8957952
#define FT_OFF3 10450944
#define FT_TOTAL 11197440

// output regions (floats)
#define OUT_Q_OFF  0
#define OUT_V_OFF  9517824
#define OUT_SP_OFF 10575360

#define NCH     45          // K chunks of 16 channels; level edges at chunks 3/9/21
#define ASTRIDE 48          // bytes per point-row in A smem (24 bf16)

// fused prep block ranges
#define TPB0 10368          // L0 transpose: 3 * 2 * 18*96
#define TPB1 15552          // +L1: 2 * 3 * 18*48
#define TPB2 18144          // +L2: 1 * 6 * 18*24
#define TPB3 20736          // +L3: 1 * 12 * 18*12
#define PRB_WBF  (TPB3 + 180)       // 20916
#define PRB_WCF  (PRB_WBF + 288)    // 21204
#define PRB_AW   (PRB_WCF + 1033)   // 22237

// ---------------- device scratch ----------------
__device__ __nv_bfloat16 d_fTb[FT_TOTAL];                  // bf16 NHWC feature maps
__device__ __align__(16) uint32_t d_wBf[45 * 8 * 32 * 4];  // sampling B frags
__device__ float d_bsum[128];                              // 0.025 * sum(be_l)
__device__ float d_aw[MROWS * 2];                          // softmax attn per (b,t1,p)
__device__ __align__(16) uint32_t d_nqh[4758912];          // new_query hi bf16 pairs
__device__ __align__(16) uint32_t d_nql[4758912];          // new_query lo bf16 pairs
__device__ __align__(16) uint32_t d_cwh[72 * 8 * 32 * 4];  // conv W hi frags
__device__ __align__(16) uint32_t d_cwl[72 * 8 * 32 * 4];  // conv W lo frags

// ---------------- helpers ----------------
__device__ __forceinline__ uint32_t smem_to_u32(const void* p) {
    uint32_t a;
    asm("{ .reg .u64 t; cvta.to.shared.u64 t, %1; cvt.u32.u64 %0, t; }" : "=r"(a) : "l"(p));
    return a;
}
__device__ __forceinline__ void ldsm_x4(uint32_t* a, uint32_t saddr) {
    asm volatile("ldmatrix.sync.aligned.m8n8.x4.shared.b16 {%0,%1,%2,%3}, [%4];"
                 : "=r"(a[0]), "=r"(a[1]), "=r"(a[2]), "=r"(a[3]) : "r"(saddr));
}
__device__ __forceinline__ void mma16816(float* d, const uint32_t* a, uint32_t b0, uint32_t b1) {
    asm volatile(
        "mma.sync.aligned.m16n8k16.row.col.f32.bf16.bf16.f32 "
        "{%0,%1,%2,%3}, {%4,%5,%6,%7}, {%8,%9}, {%0,%1,%2,%3};"
        : "+f"(d[0]), "+f"(d[1]), "+f"(d[2]), "+f"(d[3])
        : "r"(a[0]), "r"(a[1]), "r"(a[2]), "r"(a[3]), "r"(b0), "r"(b1));
}
#define FMA_BF16X2(r, a, b, c) \
    asm("fma.rn.bf16x2 %0, %1, %2, %3;" : "=r"(r) : "r"(a), "r"(b), "r"(c))
#define CVT_BF16X2_BCAST(r, f) \
    asm("cvt.rn.bf16x2.f32 %0, %1, %2;" : "=r"(r) : "f"(f), "f"(f))

__device__ __forceinline__ uint32_t pack_hi(float x, float y) {
    __nv_bfloat16 hx = __float2bfloat16_rn(x);
    __nv_bfloat16 hy = __float2bfloat16_rn(y);
    return (uint32_t)__bfloat16_as_ushort(hx) | ((uint32_t)__bfloat16_as_ushort(hy) << 16);
}
__device__ __forceinline__ uint32_t pack_lo(float x, float y, uint32_t hi) {
    float hx = __bfloat162float(__ushort_as_bfloat16((unsigned short)(hi & 0xFFFF)));
    float hy = __bfloat162float(__ushort_as_bfloat16((unsigned short)(hi >> 16)));
    __nv_bfloat16 lx = __float2bfloat16_rn(x - hx);
    __nv_bfloat16 ly = __float2bfloat16_rn(y - hy);
    return (uint32_t)__bfloat16_as_ushort(lx) | ((uint32_t)__bfloat16_as_ushort(ly) << 16);
}

__device__ __forceinline__ float dot4(float4 a, float4 b) {
    return a.x * b.x + a.y * b.y + a.z * b.z + a.w * b.w;
}

// ---------------- fused prep: transpose + weight frags + bsum + attn softmax ----------------
__global__ void __launch_bounds__(256) prep_kernel(
    const float* __restrict__ f0, const float* __restrict__ f1,
    const float* __restrict__ f2, const float* __restrict__ f3,
    const float* __restrict__ we0, const float* __restrict__ we1,
    const float* __restrict__ we2, const float* __restrict__ we3,
    const float* __restrict__ be0, const float* __restrict__ be1,
    const float* __restrict__ be2, const float* __restrict__ be3,
    const float* __restrict__ value,
    const float* __restrict__ w_attn, const float* __restrict__ b_attn,
    const float* __restrict__ cwv) {
    __shared__ float tile[32][33];
    int b = blockIdx.x;
    int t = threadIdx.x;

    if (b < TPB3) {
        // ---- feature transpose NCHW fp32 -> NHWC bf16 ----
        const float* in;
        int C, H, W, outOff, xb, cb, nz;
        if (b < TPB0) {
            in = f0; C = 48; H = 96; W = 72; outOff = FT_OFF0;
            int r = b; xb = r % 3; r /= 3; cb = r % 2; nz = r / 2;
        } else if (b < TPB1) {
            in = f1; C = 96; H = 48; W = 36; outOff = FT_OFF1;
            int r = b - TPB0; xb = r % 2; r /= 2; cb = r % 3; nz = r / 3;
        } else if (b < TPB2) {
            in = f2; C = 192; H = 24; W = 18; outOff = FT_OFF2;
            int r = b - TPB1; xb = 0; cb = r % 6; nz = r / 6;
        } else {
            in = f3; C = 384; H = 12; W = 9; outOff = FT_OFF3;
            int r = b - TPB2; xb = 0; cb = r % 12; nz = r / 12;
        }
        int n = nz / H, y = nz % H;
        int x0 = xb * 32, c0 = cb * 32;
        int tx = t & 31, ty = t >> 5;
#pragma unroll
        for (int k = 0; k < 4; k++) {
            int c = c0 + ty + 8 * k, x = x0 + tx;
            if (c < C && x < W)
                tile[ty + 8 * k][tx] = in[((size_t)(n * C + c) * H + y) * W + x];
        }
        __syncthreads();
#pragma unroll
        for (int k = 0; k < 4; k++) {
            int x = x0 + ty + 8 * k, c = c0 + tx;
            if (c < C && x < W)
                d_fTb[outOff + ((size_t)(n * H + y) * W + x) * C + c] =
                    __float2bfloat16(tile[tx][ty + 8 * k]);
        }
    } else if (b < PRB_WBF) {
        // ---- sampling B frags + bsum ----
        int bb = b - TPB3;
        int e = bb * 256 + t;
        if (bb == 0 && t < 128) {
            d_bsum[t] = 0.025f * (be0[t] + be1[t] + be2[t] + be3[t]);
        }
        if (e < 45 * 8 * 32 * 4) {
            int q = e & 3, lane = (e >> 2) & 31, np = (e >> 7) & 7, c = e >> 10;
            int tt = q >> 1, reg = q & 1;
            int n = (np * 2 + tt) * 8 + (lane >> 2);
            int k = c * 16 + reg * 8 + 2 * (lane & 3);
            uint32_t out = 0;
#pragma unroll
            for (int h = 0; h < 2; h++) {
                int ch = k + h;
                float v;
                if (ch < 48)       v = we0[n * 48 + ch];
                else if (ch < 144) v = we1[n * 96 + (ch - 48)];
                else if (ch < 336) v = we2[n * 192 + (ch - 144)];
                else               v = we3[n * 384 + (ch - 336)];
                __nv_bfloat16 bv = __float2bfloat16(v);
                out |= (uint32_t)__bfloat16_as_ushort(bv) << (16 * h);
            }
            d_wBf[e] = out;
        }
    } else if (b < PRB_WCF) {
        // ---- conv W hi/lo fragments ----
        int e = (b - PRB_WBF) * 256 + t;
        if (e < 72 * 8 * 32 * 4) {
            int q = e & 3, lane = (e >> 2) & 31, np = (e >> 7) & 7, kc = e >> 10;
            int tt = q >> 1, reg = q & 1;
            int n = (np * 2 + tt) * 8 + (lane >> 2);
            int kf = kc * 16 + reg * 8 + 2 * (lane & 3);
            uint32_t oh = 0, ol = 0;
#pragma unroll
            for (int h = 0; h < 2; h++) {
                int kfe = kf + h;
                int k = kfe >> 7, c = kfe & 127;
                float v = cwv[((size_t)n * 128 + c) * 9 + k];
                __nv_bfloat16 bh = __float2bfloat16_rn(v);
                float r = v - __bfloat162float(bh);
                __nv_bfloat16 bl = __float2bfloat16_rn(r);
                oh |= (uint32_t)__bfloat16_as_ushort(bh) << (16 * h);
                ol |= (uint32_t)__bfloat16_as_ushort(bl) << (16 * h);
            }
            d_cwh[e] = oh;
            d_cwl[e] = ol;
        }
    } else {
        // ---- attention softmax, one row per (b,t1,p) ----
        int w = (b - PRB_WCF) * 8 + (t >> 5);
        if (w >= MROWS) return;
        int lane = t & 31;
        const float4* v4 = (const float4*)value;
        const float4* wa4 = (const float4*)w_attn;
        float4 vv = v4[(size_t)w * 32 + lane];
        float e0 = dot4(vv, wa4[lane]);
        float e1 = dot4(vv, wa4[32 + lane]);
#pragma unroll
        for (int s = 16; s; s >>= 1) {
            e0 += __shfl_xor_sync(0xFFFFFFFFu, e0, s);
            e1 += __shfl_xor_sync(0xFFFFFFFFu, e1, s);
        }
        if (lane == 0) {
            float l0 = e0 + b_attn[0], l1 = e1 + b_attn[1];
            float m = fmaxf(l0, l1);
            float x0 = expf(l0 - m), x1 = expf(l1 - m);
            float inv = 1.0f / (x0 + x1);
            d_aw[2 * w] = x0 * inv;
            d_aw[2 * w + 1] = x1 * inv;
        }
    }
}

// ---------------- sampling positions (uses precomputed aw) ----------------
__global__ void pos_kernel(const float* __restrict__ query, const float* __restrict__ key,
                           const float* __restrict__ w_off, const float* __restrict__ b_off,
                           float* __restrict__ spo) {
    int w = blockIdx.x * 8 + (threadIdx.x >> 5);
    if (w >= NPTS) return;
    int lane = threadIdx.x & 31;

    const float4* q4 = (const float4*)query;
    const float4* wo4 = (const float4*)w_off;
    float4 qv = q4[(size_t)w * 32 + lane];
    float d0 = dot4(qv, wo4[lane]);
    float d1 = dot4(qv, wo4[32 + lane]);

#pragma unroll
    for (int s = 16; s; s >>= 1) {
        d0 += __shfl_xor_sync(0xFFFFFFFFu, d0, s);
        d1 += __shfl_xor_sync(0xFFFFFFFFu, d1, s);
    }
    if (lane == 0) {
        float o0 = tanhf(d0 + b_off[0]);
        float o1 = tanhf(d1 + b_off[1]);
        int bt1 = w / PK;
        int p = (w % PK) % PP;
        int ai = bt1 * PP + p;
        spo[2 * w]     = key[2 * w]     + o0 * d_aw[2 * ai];
        spo[2 * w + 1] = key[2 * w + 1] + o1 * d_aw[2 * ai + 1];
    }
}

// ---------------- bilinear geometry ----------------
__device__ __forceinline__ void geomcalc(bool valid, float gx, float gy, int n, int lvl,
                                         int4& o, float4& wv) {
    const int Hs[4] = {96, 48, 24, 12};
    const int Ws[4] = {72, 36, 18, 9};
    const int Cs[4] = {48, 96, 192, 384};
    const int FO[4] = {FT_OFF0, FT_OFF1, FT_OFF2, FT_OFF3};
    o = make_int4(0, 0, 0, 0);
    wv = make_float4(0.f, 0.f, 0.f, 0.f);
    if (!valid) return;
    int H = Hs[lvl], W = Ws[lvl], C = Cs[lvl];
    float ix = ((gx + 1.f) * (float)W - 1.f) * 0.5f;
    float iy = ((gy + 1.f) * (float)H - 1.f) * 0.5f;
    float fx = floorf(ix), fy = floorf(iy);
    int x0 = (int)fx, y0 = (int)fy;
    float wx1 = ix - fx, wy1 = iy - fy;
    float wx0 = 1.f - wx1, wy0 = 1.f - wy1;
    int base = FO[lvl] + n * (H * W * C);
    bool vx0 = (unsigned)x0 < (unsigned)W;
    bool vx1 = (unsigned)(x0 + 1) < (unsigned)W;
    bool vy0 = (unsigned)y0 < (unsigned)H;
    bool vy1 = (unsigned)(y0 + 1) < (unsigned)H;
    int r0 = y0 * W, r1 = r0 + W;
    if (vy0 && vx0) { o.x = base + (r0 + x0) * C;     wv.x = wy0 * wx0; }
    if (vy0 && vx1) { o.y = base + (r0 + x0 + 1) * C; wv.y = wy0 * wx1; }
    if (vy1 && vx0) { o.z = base + (r1 + x0) * C;     wv.z = wy1 * wx0; }
    if (vy1 && vx1) { o.w = base + (r1 + x0 + 1) * C; wv.w = wy1 * wx1; }
}

// ---------------- gather: 2 threads/point, thread h owns channel half h ----------------
__device__ __forceinline__ void gather_load3(int cn, int tid, const int4* goff,
                                             const uint4* fp4, uint4 ca[4], int& cidx) {
    int h = tid & 1, pt = tid >> 1;
    int ch0 = cn * 16;
    int lvl = (ch0 < 48) ? 0 : (ch0 < 144) ? 1 : (ch0 < 336) ? 2 : 3;
    int gb  = (lvl == 0) ? 0 : (lvl == 1) ? 48 : (lvl == 2) ? 144 : 336;
    int chl = ch0 - gb + h * 8;
    cidx = lvl * 128 + pt;
    int4 o = goff[cidx];
    ca[0] = fp4[(o.x + chl) >> 3];
    ca[1] = fp4[(o.y + chl) >> 3];
    ca[2] = fp4[(o.z + chl) >> 3];
    ca[3] = fp4[(o.w + chl) >> 3];
}

__device__ __forceinline__ void gather_store3(int tid, const float4* gwv,
                                              uint4 ca[4], int cidx,
                                              unsigned char* abuf) {
    int h = tid & 1, pt = tid >> 1;
    float4 wv = gwv[cidx];
    uint32_t w00, w01, w10, w11;
    CVT_BF16X2_BCAST(w00, wv.x);
    CVT_BF16X2_BCAST(w01, wv.y);
    CVT_BF16X2_BCAST(w10, wv.z);
    CVT_BF16X2_BCAST(w11, wv.w);
    const uint32_t* c0 = (const uint32_t*)&ca[0];
    const uint32_t* c1 = (const uint32_t*)&ca[1];
    const uint32_t* c2 = (const uint32_t*)&ca[2];
    const uint32_t* c3 = (const uint32_t*)&ca[3];
    uint32_t out[4];
#pragma unroll
    for (int j = 0; j < 4; j++) {
        uint32_t t = 0;
        FMA_BF16X2(t, c0[j], w00, t);
        FMA_BF16X2(t, c1[j], w01, t);
        FMA_BF16X2(t, c2[j], w10, t);
        FMA_BF16X2(t, c3[j], w11, t);
        out[j] = t;
    }
    *(uint4*)(abuf + pt * ASTRIDE + h * 16) =
        make_uint4(out[0], out[1], out[2], out[3]);
}

// ---------------- main: mma.sync bf16 GEMM (unchanged from R14) ----------------
__global__ void __launch_bounds__(256) main3_kernel(
    const float* __restrict__ sp, const float* __restrict__ query,
    float* __restrict__ outq) {
    __shared__ __align__(16) unsigned char abuf[2][128 * ASTRIDE];
    __shared__ int4 goff[512];
    __shared__ float4 gwv[512];

    int tid = threadIdx.x;
    int lane = tid & 31, wid = tid >> 5;
    int warp_m = wid & 3, warp_n = wid >> 2;
    int qb = blockIdx.x * 128;

#pragma unroll
    for (int s = 0; s < 2; s++) {
        int task = s * 256 + tid;
        int lvl = task >> 7, pt = task & 127;
        int q = qb + pt;
        bool valid = q < NPTS;
        float gx = 0.f, gy = 0.f;
        int n = 0;
        if (valid) {
            gx = sp[2 * q];
            gy = sp[2 * q + 1];
            n = q / 4131;
        }
        int4 o; float4 wv;
        geomcalc(valid, gx, gy, n, lvl, o, wv);
        goff[task] = o;
        gwv[task] = wv;
    }
    __syncthreads();

    float d[2][8][4];
#pragma unroll
    for (int i = 0; i < 2; i++)
#pragma unroll
        for (int j = 0; j < 8; j++)
#pragma unroll
            for (int k = 0; k < 4; k++) d[i][j][k] = 0.f;

    const uint4* fp4 = (const uint4*)d_fTb;
    const uint4* wB4 = (const uint4*)d_wBf;
    uint32_t abase = smem_to_u32(abuf);

    uint4 ca[4];
    int cidx;
    uint4 bcur[4], bnext[4];

    gather_load3(0, tid, goff, fp4, ca, cidx);
#pragma unroll
    for (int i = 0; i < 4; i++)
        bcur[i] = wB4[(warp_n * 4 + i) * 32 + lane];
    gather_store3(tid, gwv, ca, cidx, abuf[0]);
    __syncthreads();

#pragma unroll 1
    for (int c = 0; c < NCH; c++) {
        bool more = (c + 1) < NCH;
        if (more) {
            gather_load3(c + 1, tid, goff, fp4, ca, cidx);
#pragma unroll
            for (int i = 0; i < 4; i++)
                bnext[i] = wB4[((c + 1) * 8 + warp_n * 4 + i) * 32 + lane];
        }

        uint32_t a[2][4];
        uint32_t ab = abase + (c & 1) * (128 * ASTRIDE) +
                      (warp_m * 32 + (lane & 15)) * ASTRIDE + (lane >> 4) * 16;
        ldsm_x4(a[0], ab);
        ldsm_x4(a[1], ab + 16 * ASTRIDE);
#pragma unroll
        for (int nt = 0; nt < 8; nt++) {
            uint32_t b0 = (nt & 1) ? bcur[nt >> 1].z : bcur[nt >> 1].x;
            uint32_t b1 = (nt & 1) ? bcur[nt >> 1].w : bcur[nt >> 1].y;
            mma16816(d[0][nt], a[0], b0, b1);
            mma16816(d[1][nt], a[1], b0, b1);
        }

        if (more) {
            gather_store3(tid, gwv, ca, cidx, abuf[(c + 1) & 1]);
#pragma unroll
            for (int i = 0; i < 4; i++) bcur[i] = bnext[i];
        }
        __syncthreads();
    }

    // ---- epilogue: blend + store fp32 + hi/lo bf16 for the conv GEMM ----
#pragma unroll
    for (int mt = 0; mt < 2; mt++) {
#pragma unroll
        for (int rr = 0; rr < 2; rr++) {
            int q = qb + warp_m * 32 + mt * 16 + rr * 8 + (lane >> 2);
            if (q < NPTS) {
#pragma unroll
                for (int nt = 0; nt < 8; nt++) {
                    int o = warp_n * 64 + nt * 8 + 2 * (lane & 3);
                    float2 qv = *(const float2*)&query[(size_t)q * 128 + o];
                    float2 bsv = *(const float2*)&d_bsum[o];
                    float2 r;
                    r.x = 0.025f * d[mt][nt][rr * 2 + 0] + bsv.x + 0.9f * qv.x;
                    r.y = 0.025f * d[mt][nt][rr * 2 + 1] + bsv.y + 0.9f * qv.y;
                    *(float2*)&outq[(size_t)q * 128 + o] = r;
                    uint32_t hi = pack_hi(r.x, r.y);
                    uint32_t lo = pack_lo(r.x, r.y, hi);
                    int ui = q * 64 + (o >> 1);
                    d_nqh[ui] = hi;
                    d_nql[ui] = lo;
                }
            }
        }
    }
}

// ---------------- conv as split-precision bf16 GEMM ----------------
__global__ void __launch_bounds__(256) conv2_kernel(const float* __restrict__ conv_b,
                                                    float* __restrict__ nv) {
    __shared__ __align__(16) unsigned char ah[64 * 128];
    __shared__ __align__(16) unsigned char al[64 * 128];

    int tid = threadIdx.x;
    int lane = tid & 31, wid = tid >> 5;
    int warp_m = wid & 1, warp_n = wid >> 1;
    int m0 = blockIdx.x * 64;

    float d[2][4][4];
#pragma unroll
    for (int i = 0; i < 2; i++)
#pragma unroll
        for (int j = 0; j < 4; j++)
#pragma unroll
            for (int k = 0; k < 4; k++) d[i][j][k] = 0.f;

    const uint4* nqh4 = (const uint4*)d_nqh;
    const uint4* nql4 = (const uint4*)d_nql;
    const uint4* cwh4 = (const uint4*)d_cwh;
    const uint4* cwl4 = (const uint4*)d_cwl;
    uint32_t ahb = smem_to_u32(ah);
    uint32_t alb = smem_to_u32(al);

#pragma unroll 1
    for (int it = 0; it < 18; it++) {
        __syncthreads();
#pragma unroll
        for (int j = 0; j < 2; j++) {
            int idx = tid * 2 + j;
            int row = idx >> 3, cu = idx & 7;
            int m = m0 + row;
            int mc = (m < MROWS) ? m : MROWS - 1;
            int g = mc * 144 + it * 8 + cu;
            int soff = row * 128 + ((cu ^ (row & 7)) * 16);
            *(uint4*)(ah + soff) = nqh4[g];
            *(uint4*)(al + soff) = nql4[g];
        }
        __syncthreads();

#pragma unroll
        for (int kt = 0; kt < 4; kt++) {
            int kc = it * 4 + kt;
            uint4 bh0 = cwh4[((kc * 8) + 2 * warp_n + 0) * 32 + lane];
            uint4 bh1 = cwh4[((kc * 8) + 2 * warp_n + 1) * 32 + lane];
            uint4 bl0 = cwl4[((kc * 8) + 2 * warp_n + 0) * 32 + lane];
            uint4 bl1 = cwl4[((kc * 8) + 2 * warp_n + 1) * 32 + lane];
            uint32_t a_h[2][4], a_l[2][4];
#pragma unroll
            for (int mt = 0; mt < 2; mt++) {
                int row = warp_m * 32 + mt * 16 + (lane & 15);
                int cu = kt * 2 + (lane >> 4);
                uint32_t addr = row * 128 + ((cu ^ (row & 7)) * 16);
                ldsm_x4(a_h[mt], ahb + addr);
                ldsm_x4(a_l[mt], alb + addr);
            }
#pragma unroll
            for (int mt = 0; mt < 2; mt++) {
#pragma unroll
                for (int nt = 0; nt < 4; nt++) {
                    uint4 bh = (nt >> 1) ? bh1 : bh0;
                    uint4 bl = (nt >> 1) ? bl1 : bl0;
                    uint32_t bh_0 = (nt & 1) ? bh.z : bh.x;
                    uint32_t bh_1 = (nt & 1) ? bh.w : bh.y;
                    uint32_t bl_0 = (nt & 1) ? bl.z : bl.x;
                    uint32_t bl_1 = (nt & 1) ? bl.w : bl.y;
                    mma16816(d[mt][nt], a_h[mt], bh_0, bh_1);
                    mma16816(d[mt][nt], a_h[mt], bl_0, bl_1);
                    mma16816(d[mt][nt], a_l[mt], bh_0, bh_1);
                }
            }
        }
    }

#pragma unroll
    for (int mt = 0; mt < 2; mt++) {
#pragma unroll
        for (int rr = 0; rr < 2; rr++) {
            int m = m0 + warp_m * 32 + mt * 16 + rr * 8 + (lane >> 2);
            if (m < MROWS) {
#pragma unroll
                for (int nt = 0; nt < 4; nt++) {
                    int o = warp_n * 32 + nt * 8 + 2 * (lane & 3);
                    float2 cb = *(const float2*)&conv_b[o];
                    float2 r;
                    r.x = d[mt][nt][rr * 2 + 0] + cb.x;
                    r.y = d[mt][nt][rr * 2 + 1] + cb.y;
                    *(float2*)&nv[(size_t)m * 128 + o] = r;
                }
            }
        }
    }
}

// ---------------- launch ----------------
extern "C" void kernel_launch(void* const* d_in, const int* in_sizes, int n_in,
                              void* d_out, int out_size) {
    const float* f0     = (const float*)d_in[0];
    const float* f1     = (const float*)d_in[1];
    const float* f2     = (const float*)d_in[2];
    const float* f3     = (const float*)d_in[3];
    const float* query  = (const float*)d_in[4];
    const float* key    = (const float*)d_in[5];
    const float* value  = (const float*)d_in[6];
    const float* w_off  = (const float*)d_in[7];
    const float* b_off  = (const float*)d_in[8];
    const float* w_attn = (const float*)d_in[9];
    const float* b_attn = (const float*)d_in[10];
    const float* we0    = (const float*)d_in[11];
    const float* be0    = (const float*)d_in[12];
    const float* we1    = (const float*)d_in[13];
    const float* be1    = (const float*)d_in[14];
    const float* we2    = (const float*)d_in[15];
    const float* be2    = (const float*)d_in[16];
    const float* we3    = (const float*)d_in[17];
    const float* be3    = (const float*)d_in[18];
    const float* conv_w = (const float*)d_in[19];
    const float* conv_b = (const float*)d_in[20];

    float* out   = (float*)d_out;
    float* outQ  = out + OUT_Q_OFF;
    float* outV  = out + OUT_V_OFF;
    float* outSP = out + OUT_SP_OFF;

    prep_kernel<<<PRB_AW, 256>>>(f0, f1, f2, f3, we0, we1, we2, we3,
                                 be0, be1, be2, be3, value, w_attn, b_attn, conv_w);
    pos_kernel<<<9295, 256>>>(query, key, w_off, b_off, outSP);
    main3_kernel<<<(NPTS + 127) / 128, 256>>>(outSP, query, outQ);
    conv2_kernel<<<(MROWS + 63) / 64, 256>>>(conv_b, outV);
}